// round 9
// baseline (speedup 1.0000x reference)
#include <cuda_runtime.h>
#include <cuda_bf16.h>
#include <math.h>

// Problem dims
#define BB 32
#define TT 256
#define EE 512
#define HH 512
#define GG 2048   // 4*H
#define CC 9
#define MTOT (BB*TT)          // 8192
#define LSTM_BLOCKS 128       // 64 per direction
#define LP 516                // padded pitch (words) for Ws / hs rows
#define LSTM_SMEM_FLOATS (64*LP + 8192)
#define LSTM_SMEM_BYTES (LSTM_SMEM_FLOATS*4)

// ---------------- device scratch (static, no runtime allocation) -------------
__device__ float g_x[MTOT*EE];                 // gathered embeddings [m][512]
__device__ float g_xp[2L*TT*BB*GG];            // [d][t][blk(64)][typ(4)][b(32)][col(8)]
__device__ float g_hcat[(size_t)MTOT*1024];    // [b*256+t][hf(512)|hb(512)]
__device__ float g_hst[2*2*BB*HH];             // [par][dir][b][k]  double buffer
__device__ float g_emis[MTOT*CC];              // [b*256+t][9]
__device__ float g_llh[BB];
__device__ int   g_cnt[2][TT];                 // per-direction step counters
__device__ unsigned g_barcnt;                  // zero-initialized at load
__device__ unsigned g_bargen;
__device__ int   g_dummy_sink;

__device__ __forceinline__ int ld_acq(const int* p) {
    int v;
    asm volatile("ld.acquire.gpu.global.b32 %0, [%1];" : "=r"(v) : "l"(p));
    return v;
}
__device__ __forceinline__ void red_add_rel(int* p) {
    asm volatile("red.release.gpu.global.add.s32 [%0], %1;" :: "l"(p), "r"(1) : "memory");
}

// ---------------- kernel 1: embedding gather (zero row 0) --------------------
__global__ void k_gather(const int* __restrict__ inp, const float* __restrict__ emb) {
    int m = blockIdx.x;
    int tok = inp[m];
    float4* dst = (float4*)(g_x + (size_t)m * EE);
    if (tok == 0) {
        float4 z = make_float4(0.f, 0.f, 0.f, 0.f);
        for (int i = threadIdx.x; i < EE/4; i += blockDim.x) dst[i] = z;
    } else {
        const float4* src = (const float4*)(emb + (size_t)tok * EE);
        for (int i = threadIdx.x; i < EE/4; i += blockDim.x) dst[i] = src[i];
    }
}

// ---------------- kernel 2: xp = x @ W_ih^T + b_ih + b_hh  (both dirs) -------
__global__ __launch_bounds__(256, 2) void k_xpgemm(
    const float* __restrict__ wf, const float* __restrict__ wb,
    const float* __restrict__ bihf, const float* __restrict__ bhhf,
    const float* __restrict__ bihb, const float* __restrict__ bhhb)
{
    __shared__ float As[8][132];
    __shared__ float Bs[8][132];

    int ntile = blockIdx.x;            // 0..31 over 4096 cols
    int m0 = blockIdx.y * 128;
    int dir = (ntile >= 16) ? 1 : 0;
    int nloc0 = (ntile & 15) * 128;
    const float* w   = dir ? wb : wf;
    const float* bih = dir ? bihb : bihf;
    const float* bhh = dir ? bhhb : bhhf;

    int tid = threadIdx.x;
    int tx = tid & 15, ty = tid >> 4;
    int lrow = tid >> 1;
    int lk4  = (tid & 1) * 4;

    float acc[8][8];
#pragma unroll
    for (int i = 0; i < 8; i++)
#pragma unroll
        for (int j = 0; j < 8; j++) acc[i][j] = 0.f;

    for (int kt = 0; kt < EE; kt += 8) {
        float4 av = *(const float4*)(g_x + (size_t)(m0 + lrow) * EE + kt + lk4);
        float4 bv = *(const float4*)(w   + (size_t)(nloc0 + lrow) * EE + kt + lk4);
        As[lk4+0][lrow] = av.x; As[lk4+1][lrow] = av.y;
        As[lk4+2][lrow] = av.z; As[lk4+3][lrow] = av.w;
        Bs[lk4+0][lrow] = bv.x; Bs[lk4+1][lrow] = bv.y;
        Bs[lk4+2][lrow] = bv.z; Bs[lk4+3][lrow] = bv.w;
        __syncthreads();
#pragma unroll
        for (int k = 0; k < 8; k++) {
            float4 a0 = *(const float4*)&As[k][ty*4];
            float4 a1 = *(const float4*)&As[k][64 + ty*4];
            float4 b0 = *(const float4*)&Bs[k][tx*4];
            float4 b1 = *(const float4*)&Bs[k][64 + tx*4];
            float aa[8] = {a0.x,a0.y,a0.z,a0.w,a1.x,a1.y,a1.z,a1.w};
            float bb[8] = {b0.x,b0.y,b0.z,b0.w,b1.x,b1.y,b1.z,b1.w};
#pragma unroll
            for (int i = 0; i < 8; i++)
#pragma unroll
                for (int j = 0; j < 8; j++) acc[i][j] += aa[i]*bb[j];
        }
        __syncthreads();
    }

    int rws[8];
#pragma unroll
    for (int i = 0; i < 4; i++) { rws[i] = ty*4 + i; rws[4+i] = 64 + ty*4 + i; }

    float4 bias[2];
#pragma unroll
    for (int h = 0; h < 2; h++) {
        int g0 = nloc0 + h*64 + tx*4;
        bias[h] = make_float4(bih[g0+0]+bhh[g0+0], bih[g0+1]+bhh[g0+1],
                              bih[g0+2]+bhh[g0+2], bih[g0+3]+bhh[g0+3]);
    }
#pragma unroll
    for (int i = 0; i < 8; i++) {
        int m = m0 + rws[i];
        int bidx = m >> 8, t = m & 255;
        size_t tb = ((size_t)(dir*TT + t) * 64);
#pragma unroll
        for (int h = 0; h < 2; h++) {
            int g0 = nloc0 + h*64 + tx*4;
            int typ = g0 >> 9, c9 = g0 & 511;
            int blk = c9 >> 3, off = c9 & 7;        // off in {0,4}
            float4 v = make_float4(acc[i][h*4+0] + bias[h].x,
                                   acc[i][h*4+1] + bias[h].y,
                                   acc[i][h*4+2] + bias[h].z,
                                   acc[i][h*4+3] + bias[h].w);
            *(float4*)&g_xp[(tb + blk) * 1024 + typ*256 + bidx*8 + off] = v;
        }
    }
}

// ---------------- dummy kernel (keeps ncu -s window on k_lstm) ---------------
__global__ void k_dummy() { if (threadIdx.x == 1234567) g_dummy_sink = 1; }

// ---------------- kernel 3: persistent bidirectional LSTM --------------------
// 128 blocks (64/dir), 512 threads. Block owns 8 h-columns.
// Per step: per-direction aggregated barrier -> cooperative coalesced staging
// of h(t-1) into smem -> register-tiled GEMM from smem (bank-conflict-free).
__device__ __forceinline__ float sigf(float x) { return 1.f / (1.f + __expf(-x)); }

__global__ __launch_bounds__(512, 1) void k_lstm(
    const float* __restrict__ whhf, const float* __restrict__ whhb)
{
    extern __shared__ float sm[];
    float* Ws  = sm;              // [32][LP]  rows r = typ*8+col
    float* hs  = sm + 32*LP;      // [32][LP]  b-major staged h
    float* red = sm + 64*LP;      // [8 kg][4 typ][32 b][8 col]

    int bx = blockIdx.x;
    int d = bx >> 6;                   // direction
    int blk = bx & 63;
    int colbase = blk * 8;
    int tid = threadIdx.x;
    const float* whh = d ? whhb : whhf;

    // load this block's 32 W_hh rows into smem
    for (int q = tid; q < 32*128; q += 512) {
        int r = q >> 7, k4 = (q & 127) * 4;
        int grow = (r >> 3) * HH + colbase + (r & 7);
        *(float4*)(Ws + r*LP + k4) = *(const float4*)(whh + (size_t)grow * HH + k4);
    }
    // block 0 zeroes the step counters (before grid barrier; replay-safe)
    if (bx == 0) for (int q = tid; q < 2*TT; q += 512) ((int*)g_cnt)[q] = 0;
    __threadfence();
    // one-shot grid barrier (monotone generation, replay-safe)
    if (tid == 0) {
        unsigned gen = ((volatile unsigned*)&g_bargen)[0];
        if (atomicAdd(&g_barcnt, 1u) == (unsigned)(gridDim.x - 1)) {
            g_barcnt = 0u;
            __threadfence();
            atomicAdd(&g_bargen, 1u);
        } else {
            while (((volatile unsigned*)&g_bargen)[0] == gen) { }
        }
    }
    __syncthreads();

    int lane = tid & 31;
    int w = tid >> 5;
    int kg = w & 7;                    // k-slice [kg*64, kg*64+64)
    int half = w >> 3;                 // batch half: b = bg + 4*(half*4+u)
    int rg = lane >> 2;                // 0..7 gate-col within block
    int bg = lane & 3;                 // 0..3 batch group
    int pcol = tid & 7, pb = tid >> 3; // phase-2 cell (tid<256): (b=pb, col=pcol)
    float c = 0.f;

    for (int t = 0; t < TT; t++) {
        int tt = d ? (TT - 1 - t) : t;

        // prefetch xp for our cell (independent of h; overlaps barrier wait)
        float xg0 = 0.f, xg1 = 0.f, xg2 = 0.f, xg3 = 0.f;
        if (tid < 256) {
            const float* xr = g_xp + ((size_t)(d*TT + tt) * 64 + blk) * 1024 + tid;
            xg0 = xr[0]; xg1 = xr[256]; xg2 = xr[512]; xg3 = xr[768];
        }

        float acc[4][4];
#pragma unroll
        for (int i = 0; i < 4; i++)
#pragma unroll
            for (int u = 0; u < 4; u++) acc[i][u] = 0.f;

        if (t > 0) {
            // per-direction aggregated barrier: all 64 blocks finished t-1
            if (tid == 0) {
                const int* cp = &g_cnt[d][t-1];
                int miss = 0;
                while (ld_acq(cp) < 64) {
                    if (++miss > 2) __nanosleep(200);
                }
            }
            __syncthreads();   // broadcast acquire

            // cooperative coalesced staging: hs[b][k] <- h(t-1)  (64 KB)
            {
                const float* src = g_hst + (size_t)((((t+1)&1)*2 + d)*32) * 512;
#pragma unroll
                for (int i = 0; i < 8; i++) {
                    int q = i*512 + tid;
                    int b = q >> 7, k4 = (q & 127) * 4;
                    *(float4*)(hs + b*LP + k4) =
                        __ldcg((const float4*)(src + b*512 + k4));
                }
            }
            __syncthreads();

            // GEMM over this warp's k-slice, h from smem (conflict-free)
#pragma unroll 2
            for (int kc = 0; kc < 64; kc += 4) {
                int k = kg*64 + kc;
                float4 hv[4];
#pragma unroll
                for (int u = 0; u < 4; u++)
                    hv[u] = *(const float4*)(hs + (bg + 4*(half*4+u))*LP + k);
                float4 wv0 = *(const float4*)(Ws + (0*8 + rg)*LP + k);
                float4 wv1 = *(const float4*)(Ws + (1*8 + rg)*LP + k);
                float4 wv2 = *(const float4*)(Ws + (2*8 + rg)*LP + k);
                float4 wv3 = *(const float4*)(Ws + (3*8 + rg)*LP + k);
#pragma unroll
                for (int u = 0; u < 4; u++) {
                    float4 hvv = hv[u];
                    acc[0][u] += wv0.x*hvv.x; acc[0][u] += wv0.y*hvv.y;
                    acc[0][u] += wv0.z*hvv.z; acc[0][u] += wv0.w*hvv.w;
                    acc[1][u] += wv1.x*hvv.x; acc[1][u] += wv1.y*hvv.y;
                    acc[1][u] += wv1.z*hvv.z; acc[1][u] += wv1.w*hvv.w;
                    acc[2][u] += wv2.x*hvv.x; acc[2][u] += wv2.y*hvv.y;
                    acc[2][u] += wv2.z*hvv.z; acc[2][u] += wv2.w*hvv.w;
                    acc[3][u] += wv3.x*hvv.x; acc[3][u] += wv3.y*hvv.y;
                    acc[3][u] += wv3.z*hvv.z; acc[3][u] += wv3.w*hvv.w;
                }
            }
        }
        // write partials: red[kg][i][b][col]  (bank = bg*8+rg: conflict-free)
#pragma unroll
        for (int i = 0; i < 4; i++)
#pragma unroll
            for (int u = 0; u < 4; u++)
                red[kg*1024 + i*256 + (bg + 4*(half*4+u))*8 + rg] = acc[i][u];
        __syncthreads();

        // phase 2: reduce K-groups, nonlinearity, write h (threads 0..255)
        float h = 0.f;
        if (tid < 256) {
            float s0 = xg0, s1 = xg1, s2 = xg2, s3 = xg3;
#pragma unroll
            for (int g2 = 0; g2 < 8; g2++) {
                s0 += red[g2*1024 + 0*256 + tid];
                s1 += red[g2*1024 + 1*256 + tid];
                s2 += red[g2*1024 + 2*256 + tid];
                s3 += red[g2*1024 + 3*256 + tid];
            }
            c = sigf(s1) * c + sigf(s0) * tanhf(s2);
            h = sigf(s3) * tanhf(c);
            __stcg(&g_hst[((size_t)(((t&1)*2 + d)*32) + pb)*512 + colbase + pcol], h);
        }
        __syncthreads();   // h stores happen-before tid0's release-add
        if (tid == 0) red_add_rel(&g_cnt[d][t]);
        // off critical path
        if (tid < 256)
            g_hcat[((size_t)(pb*TT + tt))*1024 + d*HH + colbase + pcol] = h;
    }
}

// ---------------- kernel 4: classifier (emissions) ---------------------------
__global__ void k_cls(const float* __restrict__ cw, const float* __restrict__ cb) {
    __shared__ float hsm[1024];
    int m = blockIdx.x;
    const float4* src = (const float4*)(g_hcat + (size_t)m * 1024);
    for (int i = threadIdx.x; i < 256; i += blockDim.x) ((float4*)hsm)[i] = src[i];
    __syncthreads();
    int w = threadIdx.x >> 5, lane = threadIdx.x & 31;
    if (w < CC) {
        const float* wr = cw + w * 1024;
        float s = 0.f;
        for (int j = lane; j < 1024; j += 32) s += hsm[j] * wr[j];
#pragma unroll
        for (int off = 16; off; off >>= 1) s += __shfl_down_sync(0xffffffffu, s, off);
        if (lane == 0) g_emis[(size_t)m * CC + w] = s + cb[w];
    }
}

// ---------------- kernel 5: CRF log-likelihood (mask all-true) ---------------
__global__ void k_crf(const int* __restrict__ label, const float* __restrict__ startv,
                      const float* __restrict__ endv, const float* __restrict__ trans) {
    int b = blockIdx.x, lane = threadIdx.x;
    const int* tg = label + b * TT;
    const float* em = g_emis + (size_t)b * TT * CC;

    float p = 0.f;
    for (int t = lane; t < TT; t += 32) {
        int tag = tg[t];
        p += em[t*CC + tag];
        if (t > 0) p += trans[tg[t-1]*CC + tag];
    }
#pragma unroll
    for (int off = 16; off; off >>= 1) p += __shfl_down_sync(0xffffffffu, p, off);
    float num = __shfl_sync(0xffffffffu, p, 0);
    num += startv[tg[0]] + endv[tg[TT-1]];

    int j = (lane < CC) ? lane : 0;
    float trc[CC];
#pragma unroll
    for (int i = 0; i < CC; i++) trc[i] = trans[i*CC + j];
    float alpha = startv[j] + em[j];
    float em_next = em[CC + j];
    for (int t = 1; t < TT; t++) {
        float a[CC];
#pragma unroll
        for (int i = 0; i < CC; i++) a[i] = __shfl_sync(0xffffffffu, alpha, i) + trc[i];
        float em_t = em_next;
        if (t < TT-1) em_next = em[(t+1)*CC + j];
        float mx = a[0];
#pragma unroll
        for (int i = 1; i < CC; i++) mx = fmaxf(mx, a[i]);
        float s = 0.f;
#pragma unroll
        for (int i = 0; i < CC; i++) s += expf(a[i] - mx);
        alpha = mx + logf(s) + em_t;
    }
    float v = alpha + endv[j];
    float mv = v;
#pragma unroll
    for (int i = 0; i < CC; i++) mv = fmaxf(mv, __shfl_sync(0xffffffffu, v, i));
    float se = expf(v - mv);
    float tot = 0.f;
#pragma unroll
    for (int i = 0; i < CC; i++) tot += __shfl_sync(0xffffffffu, se, i);
    float den = mv + logf(tot);
    if (lane == 0) g_llh[b] = num - den;
}

// ---------------- kernel 6: final reduction ----------------------------------
__global__ void k_final(float* out) {
    if (threadIdx.x == 0) {
        float s = 0.f;
        for (int i = 0; i < BB; i++) s += g_llh[i];
        out[0] = -s / (float)BB;
    }
}

// ---------------- launch ------------------------------------------------------
extern "C" void kernel_launch(void* const* d_in, const int* in_sizes, int n_in,
                              void* d_out, int out_size) {
    const int*   input  = (const int*)d_in[0];
    const int*   label  = (const int*)d_in[1];
    const float* emb    = (const float*)d_in[2];
    const float* w_ih_f = (const float*)d_in[3];
    const float* w_hh_f = (const float*)d_in[4];
    const float* b_ih_f = (const float*)d_in[5];
    const float* b_hh_f = (const float*)d_in[6];
    const float* w_ih_b = (const float*)d_in[7];
    const float* w_hh_b = (const float*)d_in[8];
    const float* b_ih_b = (const float*)d_in[9];
    const float* b_hh_b = (const float*)d_in[10];
    const float* cls_w  = (const float*)d_in[11];
    const float* cls_b  = (const float*)d_in[12];
    const float* startv = (const float*)d_in[13];
    const float* endv   = (const float*)d_in[14];
    const float* trans  = (const float*)d_in[15];

    cudaFuncSetAttribute(k_lstm, cudaFuncAttributeMaxDynamicSharedMemorySize, LSTM_SMEM_BYTES);

    k_gather<<<MTOT, 128>>>(input, emb);
    k_xpgemm<<<dim3(32, 64), 256>>>(w_ih_f, w_ih_b, b_ih_f, b_hh_f, b_ih_b, b_hh_b);
    k_dummy<<<1, 32>>>();   // keeps ncu window on k_lstm
    k_lstm<<<LSTM_BLOCKS, 512, LSTM_SMEM_BYTES>>>(w_hh_f, w_hh_b);
    k_cls<<<MTOT, 288>>>(cls_w, cls_b);
    k_crf<<<BB, 32>>>(label, startv, endv, trans);
    k_final<<<1, 32>>>((float*)d_out);
}

// round 10
// speedup vs baseline: 1.5699x; 1.5699x over previous
#include <cuda_runtime.h>
#include <cuda_bf16.h>
#include <math.h>

// Problem dims
#define BB 32
#define TT 256
#define EE 512
#define HH 512
#define GG 2048   // 4*H
#define CC 9
#define MTOT (BB*TT)          // 8192
#define LSTM_BLOCKS 128       // 64 per direction
#define LP 516                // padded pitch (words) for Ws / hs rows
#define LSTM_SMEM_FLOATS (64*LP + 8192)
#define LSTM_SMEM_BYTES (LSTM_SMEM_FLOATS*4)

// ---------------- device scratch (static, no runtime allocation) -------------
__device__ float g_x[MTOT*EE];                 // gathered embeddings [m][512]
__device__ float g_xp[2L*TT*BB*GG];            // [d][t][blk(64)][typ(4)][b(32)][col(8)]
__device__ float g_hcat[(size_t)MTOT*1024];    // [b*256+t][hf(512)|hb(512)]
__device__ float g_hst[2*2*BB*HH];             // [par][dir][b][k]  double buffer
__device__ float g_emis[MTOT*CC];              // [b*256+t][9]
__device__ float g_llh[BB];
__device__ int   g_cntT[2][TT][8][32];         // tree counters, 1 line each
__device__ unsigned g_barcnt;                  // zero-initialized at load
__device__ unsigned g_bargen;
__device__ int   g_dummy_sink;

__device__ __forceinline__ int ld_acq(const int* p) {
    int v;
    asm volatile("ld.acquire.gpu.global.b32 %0, [%1];" : "=r"(v) : "l"(p));
    return v;
}
__device__ __forceinline__ void red_add_rel(int* p) {
    asm volatile("red.release.gpu.global.add.s32 [%0], %1;" :: "l"(p), "r"(1) : "memory");
}

// ---------------- kernel 1: embedding gather (zero row 0) --------------------
__global__ void k_gather(const int* __restrict__ inp, const float* __restrict__ emb) {
    int m = blockIdx.x;
    int tok = inp[m];
    float4* dst = (float4*)(g_x + (size_t)m * EE);
    if (tok == 0) {
        float4 z = make_float4(0.f, 0.f, 0.f, 0.f);
        for (int i = threadIdx.x; i < EE/4; i += blockDim.x) dst[i] = z;
    } else {
        const float4* src = (const float4*)(emb + (size_t)tok * EE);
        for (int i = threadIdx.x; i < EE/4; i += blockDim.x) dst[i] = src[i];
    }
}

// ---------------- kernel 2: xp = x @ W_ih^T + b_ih + b_hh  (both dirs) -------
__global__ __launch_bounds__(256, 2) void k_xpgemm(
    const float* __restrict__ wf, const float* __restrict__ wb,
    const float* __restrict__ bihf, const float* __restrict__ bhhf,
    const float* __restrict__ bihb, const float* __restrict__ bhhb)
{
    __shared__ float As[8][132];
    __shared__ float Bs[8][132];

    int ntile = blockIdx.x;            // 0..31 over 4096 cols
    int m0 = blockIdx.y * 128;
    int dir = (ntile >= 16) ? 1 : 0;
    int nloc0 = (ntile & 15) * 128;
    const float* w   = dir ? wb : wf;
    const float* bih = dir ? bihb : bihf;
    const float* bhh = dir ? bhhb : bhhf;

    int tid = threadIdx.x;
    int tx = tid & 15, ty = tid >> 4;
    int lrow = tid >> 1;
    int lk4  = (tid & 1) * 4;

    float acc[8][8];
#pragma unroll
    for (int i = 0; i < 8; i++)
#pragma unroll
        for (int j = 0; j < 8; j++) acc[i][j] = 0.f;

    for (int kt = 0; kt < EE; kt += 8) {
        float4 av = *(const float4*)(g_x + (size_t)(m0 + lrow) * EE + kt + lk4);
        float4 bv = *(const float4*)(w   + (size_t)(nloc0 + lrow) * EE + kt + lk4);
        As[lk4+0][lrow] = av.x; As[lk4+1][lrow] = av.y;
        As[lk4+2][lrow] = av.z; As[lk4+3][lrow] = av.w;
        Bs[lk4+0][lrow] = bv.x; Bs[lk4+1][lrow] = bv.y;
        Bs[lk4+2][lrow] = bv.z; Bs[lk4+3][lrow] = bv.w;
        __syncthreads();
#pragma unroll
        for (int k = 0; k < 8; k++) {
            float4 a0 = *(const float4*)&As[k][ty*4];
            float4 a1 = *(const float4*)&As[k][64 + ty*4];
            float4 b0 = *(const float4*)&Bs[k][tx*4];
            float4 b1 = *(const float4*)&Bs[k][64 + tx*4];
            float aa[8] = {a0.x,a0.y,a0.z,a0.w,a1.x,a1.y,a1.z,a1.w};
            float bb[8] = {b0.x,b0.y,b0.z,b0.w,b1.x,b1.y,b1.z,b1.w};
#pragma unroll
            for (int i = 0; i < 8; i++)
#pragma unroll
                for (int j = 0; j < 8; j++) acc[i][j] += aa[i]*bb[j];
        }
        __syncthreads();
    }

    int rws[8];
#pragma unroll
    for (int i = 0; i < 4; i++) { rws[i] = ty*4 + i; rws[4+i] = 64 + ty*4 + i; }

    float4 bias[2];
#pragma unroll
    for (int h = 0; h < 2; h++) {
        int g0 = nloc0 + h*64 + tx*4;
        bias[h] = make_float4(bih[g0+0]+bhh[g0+0], bih[g0+1]+bhh[g0+1],
                              bih[g0+2]+bhh[g0+2], bih[g0+3]+bhh[g0+3]);
    }
#pragma unroll
    for (int i = 0; i < 8; i++) {
        int m = m0 + rws[i];
        int bidx = m >> 8, t = m & 255;
        size_t tb = ((size_t)(dir*TT + t) * 64);
#pragma unroll
        for (int h = 0; h < 2; h++) {
            int g0 = nloc0 + h*64 + tx*4;
            int typ = g0 >> 9, c9 = g0 & 511;
            int blk = c9 >> 3, off = c9 & 7;        // off in {0,4}
            float4 v = make_float4(acc[i][h*4+0] + bias[h].x,
                                   acc[i][h*4+1] + bias[h].y,
                                   acc[i][h*4+2] + bias[h].z,
                                   acc[i][h*4+3] + bias[h].w);
            *(float4*)&g_xp[(tb + blk) * 1024 + typ*256 + bidx*8 + off] = v;
        }
    }
}

// ---------------- dummy kernel (keeps ncu -s window on k_lstm) ---------------
__global__ void k_dummy() { if (threadIdx.x == 1234567) g_dummy_sink = 1; }

// ---------------- kernel 3: persistent bidirectional LSTM --------------------
// 128 blocks (64/dir), 512 threads. Block owns 8 h-columns.
// Tree barrier (8 sub-counters/line-separated) + per-warp private staging.
__device__ __forceinline__ float sigf(float x) { return 1.f / (1.f + __expf(-x)); }

__global__ __launch_bounds__(512, 1) void k_lstm(
    const float* __restrict__ whhf, const float* __restrict__ whhb)
{
    extern __shared__ float sm[];
    float* Ws  = sm;              // [32][LP]  rows r = typ*8+col
    float* hs  = sm + 32*LP;      // [32][LP]  b-major staged h (per-warp tiles)
    float* red = sm + 64*LP;      // [8 kg][4 typ][32 b][8 col]

    int bx = blockIdx.x;
    int d = bx >> 6;                   // direction
    int blk = bx & 63;
    int colbase = blk * 8;
    int tid = threadIdx.x;
    const float* whh = d ? whhb : whhf;

    // load this block's 32 W_hh rows into smem
    for (int q = tid; q < 32*128; q += 512) {
        int r = q >> 7, k4 = (q & 127) * 4;
        int grow = (r >> 3) * HH + colbase + (r & 7);
        *(float4*)(Ws + r*LP + k4) = *(const float4*)(whh + (size_t)grow * HH + k4);
    }
    // all blocks zero their slice of the tree counters (replay-safe)
    {
        int4* cz = (int4*)g_cntT;                   // 2*256*8*32 ints = 32768 int4
        int q = bx*512 + tid;
        if (q < 32768) cz[q] = make_int4(0,0,0,0);
    }
    __threadfence();
    // one-shot grid barrier (monotone generation, replay-safe)
    if (tid == 0) {
        unsigned gen = ((volatile unsigned*)&g_bargen)[0];
        if (atomicAdd(&g_barcnt, 1u) == (unsigned)(gridDim.x - 1)) {
            g_barcnt = 0u;
            __threadfence();
            atomicAdd(&g_bargen, 1u);
        } else {
            while (((volatile unsigned*)&g_bargen)[0] == gen) { }
        }
    }
    __syncthreads();

    int lane = tid & 31;
    int w = tid >> 5;
    int kg = w & 7;                    // k-slice [kg*64, kg*64+64)
    int half = w >> 3;                 // batch half: b in [16*half, 16*half+16)
    int rg = lane >> 2;                // 0..7 gate-col within block
    int bg = lane & 3;                 // 0..3 batch group
    int pcol = tid & 7, pb = tid >> 3; // phase-2 cell (tid<256): (b=pb, col=pcol)
    float c = 0.f;

    for (int t = 0; t < TT; t++) {
        int tt = d ? (TT - 1 - t) : t;

        // prefetch xp for our cell (independent of h; overlaps barrier wait)
        float xg0 = 0.f, xg1 = 0.f, xg2 = 0.f, xg3 = 0.f;
        if (tid < 256) {
            const float* xr = g_xp + ((size_t)(d*TT + tt) * 64 + blk) * 1024 + tid;
            xg0 = xr[0]; xg1 = xr[256]; xg2 = xr[512]; xg3 = xr[768];
        }

        float acc[4][4];
#pragma unroll
        for (int i = 0; i < 4; i++)
#pragma unroll
            for (int u = 0; u < 4; u++) acc[i][u] = 0.f;

        if (t > 0) {
            // tree barrier: 8 sub-counters, each must reach 8
            if (tid < 8) {
                const int* cp = &g_cntT[d][t-1][tid][0];
                int miss = 0;
                while (ld_acq(cp) < 8) {
                    if (++miss > 2) __nanosleep(150);
                }
            }
            __syncthreads();   // broadcast acquires

            // per-warp private staging: 16 b-rows x 64 k of h(t-1)  (4 KB)
            {
                const float* src = g_hst + (size_t)((((t+1)&1)*2 + d)*32) * 512;
#pragma unroll
                for (int i = 0; i < 8; i++) {
                    int q = i*32 + lane;
                    int row = q >> 4, k4 = (q & 15) * 4;
                    int b = 16*half + row;
                    *(float4*)(hs + b*LP + kg*64 + k4) =
                        __ldcg((const float4*)(src + (size_t)b*512 + kg*64 + k4));
                }
            }
            __syncwarp();      // warp reads only its own tile

            // GEMM over this warp's k-slice, h from smem (conflict-free)
#pragma unroll 2
            for (int kc = 0; kc < 64; kc += 4) {
                int k = kg*64 + kc;
                float4 hv[4];
#pragma unroll
                for (int u = 0; u < 4; u++)
                    hv[u] = *(const float4*)(hs + (bg + 4*(half*4+u))*LP + k);
                float4 wv0 = *(const float4*)(Ws + (0*8 + rg)*LP + k);
                float4 wv1 = *(const float4*)(Ws + (1*8 + rg)*LP + k);
                float4 wv2 = *(const float4*)(Ws + (2*8 + rg)*LP + k);
                float4 wv3 = *(const float4*)(Ws + (3*8 + rg)*LP + k);
#pragma unroll
                for (int u = 0; u < 4; u++) {
                    float4 hvv = hv[u];
                    acc[0][u] += wv0.x*hvv.x; acc[0][u] += wv0.y*hvv.y;
                    acc[0][u] += wv0.z*hvv.z; acc[0][u] += wv0.w*hvv.w;
                    acc[1][u] += wv1.x*hvv.x; acc[1][u] += wv1.y*hvv.y;
                    acc[1][u] += wv1.z*hvv.z; acc[1][u] += wv1.w*hvv.w;
                    acc[2][u] += wv2.x*hvv.x; acc[2][u] += wv2.y*hvv.y;
                    acc[2][u] += wv2.z*hvv.z; acc[2][u] += wv2.w*hvv.w;
                    acc[3][u] += wv3.x*hvv.x; acc[3][u] += wv3.y*hvv.y;
                    acc[3][u] += wv3.z*hvv.z; acc[3][u] += wv3.w*hvv.w;
                }
            }
        }
        // write partials: red[kg][i][b][col]  (bank = bg*8+rg: conflict-free)
#pragma unroll
        for (int i = 0; i < 4; i++)
#pragma unroll
            for (int u = 0; u < 4; u++)
                red[kg*1024 + i*256 + (bg + 4*(half*4+u))*8 + rg] = acc[i][u];
        __syncthreads();

        // phase 2: reduce K-groups, nonlinearity, write h (threads 0..255)
        float h = 0.f;
        if (tid < 256) {
            float s0 = xg0, s1 = xg1, s2 = xg2, s3 = xg3;
#pragma unroll
            for (int g2 = 0; g2 < 8; g2++) {
                s0 += red[g2*1024 + 0*256 + tid];
                s1 += red[g2*1024 + 1*256 + tid];
                s2 += red[g2*1024 + 2*256 + tid];
                s3 += red[g2*1024 + 3*256 + tid];
            }
            c = sigf(s1) * c + sigf(s0) * tanhf(s2);
            h = sigf(s3) * tanhf(c);
            __stcg(&g_hst[((size_t)(((t&1)*2 + d)*32) + pb)*512 + colbase + pcol], h);
        }
        __syncthreads();   // h stores happen-before tid0's release-add
        if (tid == 0) red_add_rel(&g_cntT[d][t][bx & 7][0]);
        // off critical path
        if (tid < 256)
            g_hcat[((size_t)(pb*TT + tt))*1024 + d*HH + colbase + pcol] = h;
    }
}

// ---------------- kernel 4: classifier (emissions) ---------------------------
__global__ void k_cls(const float* __restrict__ cw, const float* __restrict__ cb) {
    __shared__ float hsm[1024];
    int m = blockIdx.x;
    const float4* src = (const float4*)(g_hcat + (size_t)m * 1024);
    for (int i = threadIdx.x; i < 256; i += blockDim.x) ((float4*)hsm)[i] = src[i];
    __syncthreads();
    int w = threadIdx.x >> 5, lane = threadIdx.x & 31;
    if (w < CC) {
        const float* wr = cw + w * 1024;
        float s = 0.f;
        for (int j = lane; j < 1024; j += 32) s += hsm[j] * wr[j];
#pragma unroll
        for (int off = 16; off; off >>= 1) s += __shfl_down_sync(0xffffffffu, s, off);
        if (lane == 0) g_emis[(size_t)m * CC + w] = s + cb[w];
    }
}

// ---------------- kernel 5: CRF log-likelihood (mask all-true) ---------------
__global__ void k_crf(const int* __restrict__ label, const float* __restrict__ startv,
                      const float* __restrict__ endv, const float* __restrict__ trans) {
    int b = blockIdx.x, lane = threadIdx.x;
    const int* tg = label + b * TT;
    const float* em = g_emis + (size_t)b * TT * CC;

    float p = 0.f;
    for (int t = lane; t < TT; t += 32) {
        int tag = tg[t];
        p += em[t*CC + tag];
        if (t > 0) p += trans[tg[t-1]*CC + tag];
    }
#pragma unroll
    for (int off = 16; off; off >>= 1) p += __shfl_down_sync(0xffffffffu, p, off);
    float num = __shfl_sync(0xffffffffu, p, 0);
    num += startv[tg[0]] + endv[tg[TT-1]];

    int j = (lane < CC) ? lane : 0;
    float trc[CC];
#pragma unroll
    for (int i = 0; i < CC; i++) trc[i] = trans[i*CC + j];
    float alpha = startv[j] + em[j];
    float em_next = em[CC + j];
    for (int t = 1; t < TT; t++) {
        float a[CC];
#pragma unroll
        for (int i = 0; i < CC; i++) a[i] = __shfl_sync(0xffffffffu, alpha, i) + trc[i];
        float em_t = em_next;
        if (t < TT-1) em_next = em[(t+1)*CC + j];
        float mx = a[0];
#pragma unroll
        for (int i = 1; i < CC; i++) mx = fmaxf(mx, a[i]);
        float s = 0.f;
#pragma unroll
        for (int i = 0; i < CC; i++) s += expf(a[i] - mx);
        alpha = mx + logf(s) + em_t;
    }
    float v = alpha + endv[j];
    float mv = v;
#pragma unroll
    for (int i = 0; i < CC; i++) mv = fmaxf(mv, __shfl_sync(0xffffffffu, v, i));
    float se = expf(v - mv);
    float tot = 0.f;
#pragma unroll
    for (int i = 0; i < CC; i++) tot += __shfl_sync(0xffffffffu, se, i);
    float den = mv + logf(tot);
    if (lane == 0) g_llh[b] = num - den;
}

// ---------------- kernel 6: final reduction ----------------------------------
__global__ void k_final(float* out) {
    if (threadIdx.x == 0) {
        float s = 0.f;
        for (int i = 0; i < BB; i++) s += g_llh[i];
        out[0] = -s / (float)BB;
    }
}

// ---------------- launch ------------------------------------------------------
extern "C" void kernel_launch(void* const* d_in, const int* in_sizes, int n_in,
                              void* d_out, int out_size) {
    const int*   input  = (const int*)d_in[0];
    const int*   label  = (const int*)d_in[1];
    const float* emb    = (const float*)d_in[2];
    const float* w_ih_f = (const float*)d_in[3];
    const float* w_hh_f = (const float*)d_in[4];
    const float* b_ih_f = (const float*)d_in[5];
    const float* b_hh_f = (const float*)d_in[6];
    const float* w_ih_b = (const float*)d_in[7];
    const float* w_hh_b = (const float*)d_in[8];
    const float* b_ih_b = (const float*)d_in[9];
    const float* b_hh_b = (const float*)d_in[10];
    const float* cls_w  = (const float*)d_in[11];
    const float* cls_b  = (const float*)d_in[12];
    const float* startv = (const float*)d_in[13];
    const float* endv   = (const float*)d_in[14];
    const float* trans  = (const float*)d_in[15];

    cudaFuncSetAttribute(k_lstm, cudaFuncAttributeMaxDynamicSharedMemorySize, LSTM_SMEM_BYTES);

    k_gather<<<MTOT, 128>>>(input, emb);
    k_xpgemm<<<dim3(32, 64), 256>>>(w_ih_f, w_ih_b, b_ih_f, b_hh_f, b_ih_b, b_hh_b);
    k_dummy<<<1, 32>>>();   // keeps ncu window on k_lstm
    k_lstm<<<LSTM_BLOCKS, 512, LSTM_SMEM_BYTES>>>(w_hh_f, w_hh_b);
    k_cls<<<MTOT, 288>>>(cls_w, cls_b);
    k_crf<<<BB, 32>>>(label, startv, endv, trans);
    k_final<<<1, 32>>>((float*)d_out);
}

// round 12
// speedup vs baseline: 1.9053x; 1.2136x over previous
#include <cuda_runtime.h>
#include <cuda_bf16.h>
#include <math.h>

// Problem dims
#define BB 32
#define TT 256
#define EE 512
#define HH 512
#define GG 2048   // 4*H
#define CC 9
#define MTOT (BB*TT)          // 8192
#define LSTM_BLOCKS 128       // 64 per direction
#define LP 516                // padded pitch (words) for Ws / hs rows
#define LSTM_SMEM_FLOATS (64*LP + 8192)
#define LSTM_SMEM_BYTES (LSTM_SMEM_FLOATS*4)

// ---------------- device scratch (static, no runtime allocation) -------------
__device__ float g_x[MTOT*EE];                 // gathered embeddings [m][512]
__device__ float g_xp[2L*TT*BB*GG];            // [d][t][blk(64)][typ(4)][b(32)][col(8)]
__device__ float g_hcat[(size_t)MTOT*1024];    // [b*256+t][hf(512)|hb(512)]
__device__ float g_hst[2*2*BB*HH];             // [par][dir][b][k]  double buffer
__device__ float g_emis[MTOT*CC];              // [b*256+t][9]
__device__ float g_llh[BB];
__device__ int   g_cntT[2][TT][8][32];         // tree counters, 1 line each
__device__ unsigned g_barcnt;                  // zero-initialized at load
__device__ unsigned g_bargen;
__device__ int   g_dummy_sink;

__device__ __forceinline__ int ld_acq(const int* p) {
    int v;
    asm volatile("ld.acquire.gpu.global.b32 %0, [%1];" : "=r"(v) : "l"(p));
    return v;
}
__device__ __forceinline__ void red_add_rel(int* p) {
    asm volatile("red.release.gpu.global.add.s32 [%0], %1;" :: "l"(p), "r"(1) : "memory");
}
__device__ __forceinline__ unsigned f2tf32(float f) {
    unsigned u;
    asm("cvt.rna.tf32.f32 %0, %1;" : "=r"(u) : "f"(f));
    return u;
}
__device__ __forceinline__ void mma_tf32(float* d, const unsigned* a, const unsigned* b) {
    asm("mma.sync.aligned.m16n8k8.row.col.f32.tf32.tf32.f32 "
        "{%0,%1,%2,%3}, {%4,%5,%6,%7}, {%8,%9}, {%0,%1,%2,%3};"
        : "+f"(d[0]), "+f"(d[1]), "+f"(d[2]), "+f"(d[3])
        : "r"(a[0]), "r"(a[1]), "r"(a[2]), "r"(a[3]), "r"(b[0]), "r"(b[1]));
}

// ---------------- kernel 1: embedding gather (zero row 0) --------------------
__global__ void k_gather(const int* __restrict__ inp, const float* __restrict__ emb) {
    int m = blockIdx.x;
    int tok = inp[m];
    float4* dst = (float4*)(g_x + (size_t)m * EE);
    if (tok == 0) {
        float4 z = make_float4(0.f, 0.f, 0.f, 0.f);
        for (int i = threadIdx.x; i < EE/4; i += blockDim.x) dst[i] = z;
    } else {
        const float4* src = (const float4*)(emb + (size_t)tok * EE);
        for (int i = threadIdx.x; i < EE/4; i += blockDim.x) dst[i] = src[i];
    }
}

// ---------------- kernel 2: xp = x @ W_ih^T + b_ih + b_hh  (tf32 tensor) -----
// 128(m) x 128(n) tile, K=512, BK=32. 8 warps: warp_m(0..3) x warp_n(0..1),
// warp tile 32x64. mma.m16n8k8 tf32, fp32 accumulate. tf32 cvt fused in staging.
#define XP 36   // smem pitch (words): banks (4g+tg) all distinct -> conflict-free
__global__ __launch_bounds__(256, 2) void k_xpgemm_tc(
    const float* __restrict__ wf, const float* __restrict__ wb,
    const float* __restrict__ bihf, const float* __restrict__ bhhf,
    const float* __restrict__ bihb, const float* __restrict__ bhhb)
{
    __shared__ float As[128*XP];   // x tile  [m][k]
    __shared__ float Bs[128*XP];   // W tile  [n][k]

    int ntile = blockIdx.x;            // 0..31 over 4096 cols
    int m0 = blockIdx.y * 128;
    int dir = (ntile >= 16) ? 1 : 0;
    int nloc0 = (ntile & 15) * 128;
    const float* w   = dir ? wb : wf;
    const float* bih = dir ? bihb : bihf;
    const float* bhh = dir ? bhhb : bhhf;

    int tid = threadIdx.x;
    int lane = tid & 31;
    int wr = tid >> 5;                 // warp 0..7
    int wm = wr >> 1, wn = wr & 1;     // warp grid 4x2
    int g = lane >> 2, tg = lane & 3;  // groupID, threadID-in-group

    // staging mapping: thread -> row tid>>1, k-half (tid&1)*16
    int srow = tid >> 1, skq = (tid & 1) * 16;

    float c[2][8][4];
#pragma unroll
    for (int mt = 0; mt < 2; mt++)
#pragma unroll
        for (int nt = 0; nt < 8; nt++)
#pragma unroll
            for (int e = 0; e < 4; e++) c[mt][nt][e] = 0.f;

    for (int kt = 0; kt < EE; kt += 32) {
        // stage + convert to tf32
        {
            const float4* ax = (const float4*)(g_x + (size_t)(m0 + srow) * EE + kt + skq);
            const float4* bx = (const float4*)(w   + (size_t)(nloc0 + srow) * EE + kt + skq);
#pragma unroll
            for (int i = 0; i < 4; i++) {
                float4 av = ax[i], bv = bx[i];
                unsigned* ad = (unsigned*)(As + srow*XP + skq + i*4);
                unsigned* bd = (unsigned*)(Bs + srow*XP + skq + i*4);
                ad[0]=f2tf32(av.x); ad[1]=f2tf32(av.y); ad[2]=f2tf32(av.z); ad[3]=f2tf32(av.w);
                bd[0]=f2tf32(bv.x); bd[1]=f2tf32(bv.y); bd[2]=f2tf32(bv.z); bd[3]=f2tf32(bv.w);
            }
        }
        __syncthreads();

#pragma unroll
        for (int ks = 0; ks < 4; ks++) {
            int kk = ks * 8;
            unsigned a[2][4];
#pragma unroll
            for (int mt = 0; mt < 2; mt++) {
                int rm = wm*32 + mt*16;
                const unsigned* A0 = (const unsigned*)(As + (rm + g)*XP + kk);
                const unsigned* A8 = (const unsigned*)(As + (rm + g + 8)*XP + kk);
                a[mt][0] = A0[tg];   a[mt][1] = A8[tg];
                a[mt][2] = A0[tg+4]; a[mt][3] = A8[tg+4];
            }
#pragma unroll
            for (int nt = 0; nt < 8; nt++) {
                int cn = wn*64 + nt*8;
                const unsigned* B0 = (const unsigned*)(Bs + (cn + g)*XP + kk);
                unsigned b[2];
                b[0] = B0[tg]; b[1] = B0[tg+4];
                mma_tf32(c[0][nt], a[0], b);
                mma_tf32(c[1][nt], a[1], b);
            }
        }
        __syncthreads();
    }

    // bias for this thread's 16 columns
    float biasv[16];
#pragma unroll
    for (int nt = 0; nt < 8; nt++)
#pragma unroll
        for (int e = 0; e < 2; e++) {
            int g0 = nloc0 + wn*64 + nt*8 + 2*tg + e;
            biasv[nt*2+e] = bih[g0] + bhh[g0];
        }

    // scatter epilogue: row = m0 + wm*32 + mt*16 + g + rh*8
#pragma unroll
    for (int mt = 0; mt < 2; mt++)
#pragma unroll
        for (int rh = 0; rh < 2; rh++) {
            int m = m0 + wm*32 + mt*16 + g + rh*8;
            int bidx = m >> 8, t = m & 255;
            size_t tb = ((size_t)(dir*TT + t) * 64);
#pragma unroll
            for (int nt = 0; nt < 8; nt++)
#pragma unroll
                for (int e = 0; e < 2; e++) {
                    int g0 = nloc0 + wn*64 + nt*8 + 2*tg + e;
                    int typ = g0 >> 9, c9 = g0 & 511;
                    g_xp[(tb + (c9 >> 3)) * 1024 + typ*256 + bidx*8 + (c9 & 7)]
                        = c[mt][nt][rh*2 + e] + biasv[nt*2+e];
                }
        }
}

// ---------------- dummy kernel (keeps ncu -s window on k_lstm) ---------------
__global__ void k_dummy() { if (threadIdx.x == 1234567) g_dummy_sink = 1; }

// ---------------- kernel 3: persistent bidirectional LSTM --------------------
// (unchanged from R10 winner: tree barrier + per-warp private staging)
__device__ __forceinline__ float sigf(float x) { return 1.f / (1.f + __expf(-x)); }

__global__ __launch_bounds__(512, 1) void k_lstm(
    const float* __restrict__ whhf, const float* __restrict__ whhb)
{
    extern __shared__ float sm[];
    float* Ws  = sm;              // [32][LP]  rows r = typ*8+col
    float* hs  = sm + 32*LP;      // [32][LP]  b-major staged h (per-warp tiles)
    float* red = sm + 64*LP;      // [8 kg][4 typ][32 b][8 col]

    int bx = blockIdx.x;
    int d = bx >> 6;                   // direction
    int blk = bx & 63;
    int colbase = blk * 8;
    int tid = threadIdx.x;
    const float* whh = d ? whhb : whhf;

    for (int q = tid; q < 32*128; q += 512) {
        int r = q >> 7, k4 = (q & 127) * 4;
        int grow = (r >> 3) * HH + colbase + (r & 7);
        *(float4*)(Ws + r*LP + k4) = *(const float4*)(whh + (size_t)grow * HH + k4);
    }
    {
        int4* cz = (int4*)g_cntT;
        int q = bx*512 + tid;
        if (q < 32768) cz[q] = make_int4(0,0,0,0);
    }
    __threadfence();
    if (tid == 0) {
        unsigned gen = ((volatile unsigned*)&g_bargen)[0];
        if (atomicAdd(&g_barcnt, 1u) == (unsigned)(gridDim.x - 1)) {
            g_barcnt = 0u;
            __threadfence();
            atomicAdd(&g_bargen, 1u);
        } else {
            while (((volatile unsigned*)&g_bargen)[0] == gen) { }
        }
    }
    __syncthreads();

    int lane = tid & 31;
    int w = tid >> 5;
    int kg = w & 7;
    int half = w >> 3;
    int rg = lane >> 2;
    int bg = lane & 3;
    int pcol = tid & 7, pb = tid >> 3;
    float c = 0.f;

    for (int t = 0; t < TT; t++) {
        int tt = d ? (TT - 1 - t) : t;

        float xg0 = 0.f, xg1 = 0.f, xg2 = 0.f, xg3 = 0.f;
        if (tid < 256) {
            const float* xr = g_xp + ((size_t)(d*TT + tt) * 64 + blk) * 1024 + tid;
            xg0 = xr[0]; xg1 = xr[256]; xg2 = xr[512]; xg3 = xr[768];
        }

        float acc[4][4];
#pragma unroll
        for (int i = 0; i < 4; i++)
#pragma unroll
            for (int u = 0; u < 4; u++) acc[i][u] = 0.f;

        if (t > 0) {
            if (tid < 8) {
                const int* cp = &g_cntT[d][t-1][tid][0];
                int miss = 0;
                while (ld_acq(cp) < 8) {
                    if (++miss > 2) __nanosleep(150);
                }
            }
            __syncthreads();

            {
                const float* src = g_hst + (size_t)((((t+1)&1)*2 + d)*32) * 512;
#pragma unroll
                for (int i = 0; i < 8; i++) {
                    int q = i*32 + lane;
                    int row = q >> 4, k4 = (q & 15) * 4;
                    int b = 16*half + row;
                    *(float4*)(hs + b*LP + kg*64 + k4) =
                        __ldcg((const float4*)(src + (size_t)b*512 + kg*64 + k4));
                }
            }
            __syncwarp();

#pragma unroll 2
            for (int kc = 0; kc < 64; kc += 4) {
                int k = kg*64 + kc;
                float4 hv[4];
#pragma unroll
                for (int u = 0; u < 4; u++)
                    hv[u] = *(const float4*)(hs + (bg + 4*(half*4+u))*LP + k);
                float4 wv0 = *(const float4*)(Ws + (0*8 + rg)*LP + k);
                float4 wv1 = *(const float4*)(Ws + (1*8 + rg)*LP + k);
                float4 wv2 = *(const float4*)(Ws + (2*8 + rg)*LP + k);
                float4 wv3 = *(const float4*)(Ws + (3*8 + rg)*LP + k);
#pragma unroll
                for (int u = 0; u < 4; u++) {
                    float4 hvv = hv[u];
                    acc[0][u] += wv0.x*hvv.x; acc[0][u] += wv0.y*hvv.y;
                    acc[0][u] += wv0.z*hvv.z; acc[0][u] += wv0.w*hvv.w;
                    acc[1][u] += wv1.x*hvv.x; acc[1][u] += wv1.y*hvv.y;
                    acc[1][u] += wv1.z*hvv.z; acc[1][u] += wv1.w*hvv.w;
                    acc[2][u] += wv2.x*hvv.x; acc[2][u] += wv2.y*hvv.y;
                    acc[2][u] += wv2.z*hvv.z; acc[2][u] += wv2.w*hvv.w;
                    acc[3][u] += wv3.x*hvv.x; acc[3][u] += wv3.y*hvv.y;
                    acc[3][u] += wv3.z*hvv.z; acc[3][u] += wv3.w*hvv.w;
                }
            }
        }
#pragma unroll
        for (int i = 0; i < 4; i++)
#pragma unroll
            for (int u = 0; u < 4; u++)
                red[kg*1024 + i*256 + (bg + 4*(half*4+u))*8 + rg] = acc[i][u];
        __syncthreads();

        float h = 0.f;
        if (tid < 256) {
            float s0 = xg0, s1 = xg1, s2 = xg2, s3 = xg3;
#pragma unroll
            for (int g2 = 0; g2 < 8; g2++) {
                s0 += red[g2*1024 + 0*256 + tid];
                s1 += red[g2*1024 + 1*256 + tid];
                s2 += red[g2*1024 + 2*256 + tid];
                s3 += red[g2*1024 + 3*256 + tid];
            }
            c = sigf(s1) * c + sigf(s0) * tanhf(s2);
            h = sigf(s3) * tanhf(c);
            __stcg(&g_hst[((size_t)(((t&1)*2 + d)*32) + pb)*512 + colbase + pcol], h);
        }
        __syncthreads();
        if (tid == 0) red_add_rel(&g_cntT[d][t][bx & 7][0]);
        if (tid < 256)
            g_hcat[((size_t)(pb*TT + tt))*1024 + d*HH + colbase + pcol] = h;
    }
}

// ---------------- kernel 4: classifier (emissions) ---------------------------
__global__ void k_cls(const float* __restrict__ cw, const float* __restrict__ cb) {
    __shared__ float hsm[1024];
    int m = blockIdx.x;
    const float4* src = (const float4*)(g_hcat + (size_t)m * 1024);
    for (int i = threadIdx.x; i < 256; i += blockDim.x) ((float4*)hsm)[i] = src[i];
    __syncthreads();
    int w = threadIdx.x >> 5, lane = threadIdx.x & 31;
    if (w < CC) {
        const float* wr = cw + w * 1024;
        float s = 0.f;
        for (int j = lane; j < 1024; j += 32) s += hsm[j] * wr[j];
#pragma unroll
        for (int off = 16; off; off >>= 1) s += __shfl_down_sync(0xffffffffu, s, off);
        if (lane == 0) g_emis[(size_t)m * CC + w] = s + cb[w];
    }
}

// ---------------- kernel 5: CRF log-likelihood (mask all-true) ---------------
__global__ void k_crf(const int* __restrict__ label, const float* __restrict__ startv,
                      const float* __restrict__ endv, const float* __restrict__ trans) {
    int b = blockIdx.x, lane = threadIdx.x;
    const int* tg = label + b * TT;
    const float* em = g_emis + (size_t)b * TT * CC;

    float p = 0.f;
    for (int t = lane; t < TT; t += 32) {
        int tag = tg[t];
        p += em[t*CC + tag];
        if (t > 0) p += trans[tg[t-1]*CC + tag];
    }
#pragma unroll
    for (int off = 16; off; off >>= 1) p += __shfl_down_sync(0xffffffffu, p, off);
    float num = __shfl_sync(0xffffffffu, p, 0);
    num += startv[tg[0]] + endv[tg[TT-1]];

    int j = (lane < CC) ? lane : 0;
    float trc[CC];
#pragma unroll
    for (int i = 0; i < CC; i++) trc[i] = trans[i*CC + j];
    float alpha = startv[j] + em[j];
    float em_next = em[CC + j];
    for (int t = 1; t < TT; t++) {
        float a[CC];
#pragma unroll
        for (int i = 0; i < CC; i++) a[i] = __shfl_sync(0xffffffffu, alpha, i) + trc[i];
        float em_t = em_next;
        if (t < TT-1) em_next = em[(t+1)*CC + j];
        float mx = a[0];
#pragma unroll
        for (int i = 1; i < CC; i++) mx = fmaxf(mx, a[i]);
        float s = 0.f;
#pragma unroll
        for (int i = 0; i < CC; i++) s += expf(a[i] - mx);
        alpha = mx + logf(s) + em_t;
    }
    float v = alpha + endv[j];
    float mv = v;
#pragma unroll
    for (int i = 0; i < CC; i++) mv = fmaxf(mv, __shfl_sync(0xffffffffu, v, i));
    float se = expf(v - mv);
    float tot = 0.f;
#pragma unroll
    for (int i = 0; i < CC; i++) tot += __shfl_sync(0xffffffffu, se, i);
    float den = mv + logf(tot);
    if (lane == 0) g_llh[b] = num - den;
}

// ---------------- kernel 6: final reduction ----------------------------------
__global__ void k_final(float* out) {
    if (threadIdx.x == 0) {
        float s = 0.f;
        for (int i = 0; i < BB; i++) s += g_llh[i];
        out[0] = -s / (float)BB;
    }
}

// ---------------- launch ------------------------------------------------------
extern "C" void kernel_launch(void* const* d_in, const int* in_sizes, int n_in,
                              void* d_out, int out_size) {
    const int*   input  = (const int*)d_in[0];
    const int*   label  = (const int*)d_in[1];
    const float* emb    = (const float*)d_in[2];
    const float* w_ih_f = (const float*)d_in[3];
    const float* w_hh_f = (const float*)d_in[4];
    const float* b_ih_f = (const float*)d_in[5];
    const float* b_hh_f = (const float*)d_in[6];
    const float* w_ih_b = (const float*)d_in[7];
    const float* w_hh_b = (const float*)d_in[8];
    const float* b_ih_b = (const float*)d_in[9];
    const float* b_hh_b = (const float*)d_in[10];
    const float* cls_w  = (const float*)d_in[11];
    const float* cls_b  = (const float*)d_in[12];
    const float* startv = (const float*)d_in[13];
    const float* endv   = (const float*)d_in[14];
    const float* trans  = (const float*)d_in[15];

    cudaFuncSetAttribute(k_lstm, cudaFuncAttributeMaxDynamicSharedMemorySize, LSTM_SMEM_BYTES);

    k_gather<<<MTOT, 128>>>(input, emb);
    k_xpgemm_tc<<<dim3(32, 64), 256>>>(w_ih_f, w_ih_b, b_ih_f, b_hh_f, b_ih_b, b_hh_b);
    k_dummy<<<1, 32>>>();   // keeps ncu window on k_lstm
    k_lstm<<<LSTM_BLOCKS, 512, LSTM_SMEM_BYTES>>>(w_hh_f, w_hh_b);
    k_cls<<<MTOT, 288>>>(cls_w, cls_b);
    k_crf<<<BB, 32>>>(label, startv, endv, trans);
    k_final<<<1, 32>>>((float*)d_out);
}

// round 13
// speedup vs baseline: 2.0069x; 1.0533x over previous
#include <cuda_runtime.h>
#include <cuda_bf16.h>
#include <math.h>

// Problem dims
#define BB 32
#define TT 256
#define EE 512
#define HH 512
#define GG 2048   // 4*H
#define CC 9
#define MTOT (BB*TT)          // 8192
#define LSTM_BLOCKS 128       // 64 per direction
#define LP 516                // padded pitch (words) for hs rows
#define LSTM_SMEM_FLOATS (32*LP + 8192)
#define LSTM_SMEM_BYTES (LSTM_SMEM_FLOATS*4)

// ---------------- device scratch (static, no runtime allocation) -------------
__device__ float g_x[MTOT*EE];                 // gathered embeddings [m][512]
__device__ float g_xp[2L*TT*BB*GG];            // [d][t][blk(64)][typ(4)][b(32)][col(8)]
__device__ float g_hcat[(size_t)MTOT*1024];    // [b*256+t][hf(512)|hb(512)]
__device__ float g_hst[2*2*BB*HH];             // [par][dir][b][k]  double buffer
__device__ float g_emis[MTOT*CC];              // [b*256+t][9]
__device__ float g_llh[BB];
__device__ int   g_cntT[2][TT][8][32];         // tree counters, 1 line each
__device__ unsigned g_barcnt;                  // zero-initialized at load
__device__ unsigned g_bargen;
__device__ int   g_dummy_sink;

__device__ __forceinline__ int ld_acq(const int* p) {
    int v;
    asm volatile("ld.acquire.gpu.global.b32 %0, [%1];" : "=r"(v) : "l"(p));
    return v;
}
__device__ __forceinline__ void red_add_rel(int* p) {
    asm volatile("red.release.gpu.global.add.s32 [%0], %1;" :: "l"(p), "r"(1) : "memory");
}
__device__ __forceinline__ unsigned f2tf32(float f) {
    unsigned u;
    asm("cvt.rna.tf32.f32 %0, %1;" : "=r"(u) : "f"(f));
    return u;
}
__device__ __forceinline__ void mma_tf32(float* d, const unsigned* a, const unsigned* b) {
    asm("mma.sync.aligned.m16n8k8.row.col.f32.tf32.tf32.f32 "
        "{%0,%1,%2,%3}, {%4,%5,%6,%7}, {%8,%9}, {%0,%1,%2,%3};"
        : "+f"(d[0]), "+f"(d[1]), "+f"(d[2]), "+f"(d[3])
        : "r"(a[0]), "r"(a[1]), "r"(a[2]), "r"(a[3]), "r"(b[0]), "r"(b[1]));
}

// ---------------- kernel 1: embedding gather (zero row 0) --------------------
__global__ void k_gather(const int* __restrict__ inp, const float* __restrict__ emb) {
    int m = blockIdx.x;
    int tok = inp[m];
    float4* dst = (float4*)(g_x + (size_t)m * EE);
    if (tok == 0) {
        float4 z = make_float4(0.f, 0.f, 0.f, 0.f);
        for (int i = threadIdx.x; i < EE/4; i += blockDim.x) dst[i] = z;
    } else {
        const float4* src = (const float4*)(emb + (size_t)tok * EE);
        for (int i = threadIdx.x; i < EE/4; i += blockDim.x) dst[i] = src[i];
    }
}

// ---------------- kernel 2: xp = x @ W_ih^T + b_ih + b_hh  (tf32 tensor) -----
#define XP 36   // smem pitch (words): banks (4g+tg) all distinct -> conflict-free
__global__ __launch_bounds__(256, 2) void k_xpgemm_tc(
    const float* __restrict__ wf, const float* __restrict__ wb,
    const float* __restrict__ bihf, const float* __restrict__ bhhf,
    const float* __restrict__ bihb, const float* __restrict__ bhhb)
{
    __shared__ float As[128*XP];   // x tile  [m][k]
    __shared__ float Bs[128*XP];   // W tile  [n][k]

    int ntile = blockIdx.x;            // 0..31 over 4096 cols
    int m0 = blockIdx.y * 128;
    int dir = (ntile >= 16) ? 1 : 0;
    int nloc0 = (ntile & 15) * 128;
    const float* w   = dir ? wb : wf;
    const float* bih = dir ? bihb : bihf;
    const float* bhh = dir ? bhhb : bhhf;

    int tid = threadIdx.x;
    int lane = tid & 31;
    int wr = tid >> 5;                 // warp 0..7
    int wm = wr >> 1, wn = wr & 1;     // warp grid 4x2
    int g = lane >> 2, tg = lane & 3;  // groupID, threadID-in-group

    int srow = tid >> 1, skq = (tid & 1) * 16;

    float c[2][8][4];
#pragma unroll
    for (int mt = 0; mt < 2; mt++)
#pragma unroll
        for (int nt = 0; nt < 8; nt++)
#pragma unroll
            for (int e = 0; e < 4; e++) c[mt][nt][e] = 0.f;

    for (int kt = 0; kt < EE; kt += 32) {
        {
            const float4* ax = (const float4*)(g_x + (size_t)(m0 + srow) * EE + kt + skq);
            const float4* bx = (const float4*)(w   + (size_t)(nloc0 + srow) * EE + kt + skq);
#pragma unroll
            for (int i = 0; i < 4; i++) {
                float4 av = ax[i], bv = bx[i];
                unsigned* ad = (unsigned*)(As + srow*XP + skq + i*4);
                unsigned* bd = (unsigned*)(Bs + srow*XP + skq + i*4);
                ad[0]=f2tf32(av.x); ad[1]=f2tf32(av.y); ad[2]=f2tf32(av.z); ad[3]=f2tf32(av.w);
                bd[0]=f2tf32(bv.x); bd[1]=f2tf32(bv.y); bd[2]=f2tf32(bv.z); bd[3]=f2tf32(bv.w);
            }
        }
        __syncthreads();

#pragma unroll
        for (int ks = 0; ks < 4; ks++) {
            int kk = ks * 8;
            unsigned a[2][4];
#pragma unroll
            for (int mt = 0; mt < 2; mt++) {
                int rm = wm*32 + mt*16;
                const unsigned* A0 = (const unsigned*)(As + (rm + g)*XP + kk);
                const unsigned* A8 = (const unsigned*)(As + (rm + g + 8)*XP + kk);
                a[mt][0] = A0[tg];   a[mt][1] = A8[tg];
                a[mt][2] = A0[tg+4]; a[mt][3] = A8[tg+4];
            }
#pragma unroll
            for (int nt = 0; nt < 8; nt++) {
                int cn = wn*64 + nt*8;
                const unsigned* B0 = (const unsigned*)(Bs + (cn + g)*XP + kk);
                unsigned b[2];
                b[0] = B0[tg]; b[1] = B0[tg+4];
                mma_tf32(c[0][nt], a[0], b);
                mma_tf32(c[1][nt], a[1], b);
            }
        }
        __syncthreads();
    }

    float biasv[16];
#pragma unroll
    for (int nt = 0; nt < 8; nt++)
#pragma unroll
        for (int e = 0; e < 2; e++) {
            int g0 = nloc0 + wn*64 + nt*8 + 2*tg + e;
            biasv[nt*2+e] = bih[g0] + bhh[g0];
        }

#pragma unroll
    for (int mt = 0; mt < 2; mt++)
#pragma unroll
        for (int rh = 0; rh < 2; rh++) {
            int m = m0 + wm*32 + mt*16 + g + rh*8;
            int bidx = m >> 8, t = m & 255;
            size_t tb = ((size_t)(dir*TT + t) * 64);
#pragma unroll
            for (int nt = 0; nt < 8; nt++)
#pragma unroll
                for (int e = 0; e < 2; e++) {
                    int g0 = nloc0 + wn*64 + nt*8 + 2*tg + e;
                    int typ = g0 >> 9, c9 = g0 & 511;
                    g_xp[(tb + (c9 >> 3)) * 1024 + typ*256 + bidx*8 + (c9 & 7)]
                        = c[mt][nt][rh*2 + e] + biasv[nt*2+e];
                }
        }
}

// ---------------- dummy kernel (keeps ncu -s window on k_lstm) ---------------
__global__ void k_dummy() { if (threadIdx.x == 1234567) g_dummy_sink = 1; }

// ---------------- kernel 3: persistent bidirectional LSTM (tf32 tensor) ------
// 128 blocks (64/dir), 512 threads. Block owns 8 h-columns (32 gate rows x 32 b).
// Warp (kg, half): 32 rows x 16 batches over K-slice kg*64..+64 via mma
// m16n8k8 tf32. W fragments RESIDENT in registers (64/thread, loaded once).
__device__ __forceinline__ float sigf(float x) { return 1.f / (1.f + __expf(-x)); }

__global__ __launch_bounds__(512, 1) void k_lstm(
    const float* __restrict__ whhf, const float* __restrict__ whhb)
{
    extern __shared__ float sm[];
    float* hs  = sm;              // [32][LP]  b-major staged h (tf32 bits)
    float* red = sm + 32*LP;      // [8 kg][4 typ][32 b][8 col]

    int bx = blockIdx.x;
    int d = bx >> 6;                   // direction
    int blk = bx & 63;
    int colbase = blk * 8;
    int tid = threadIdx.x;
    const float* whh = d ? whhb : whhf;

    int lane = tid & 31;
    int w = tid >> 5;
    int kg = w & 7;                    // k-slice [kg*64, kg*64+64)
    int half = w >> 3;                 // batches [16*half, 16*half+16)
    int g = lane >> 2, tg = lane & 3;  // mma groupID / thread-in-group
    int pcol = tid & 7, pb = tid >> 3; // phase-2 cell (tid<256)

    // ---- resident W fragments: a[mt][ks][4], rows mt*16+g(+8), k ks*8+tg(+4)
    unsigned a[2][8][4];
#pragma unroll
    for (int mt = 0; mt < 2; mt++)
#pragma unroll
        for (int ks = 0; ks < 8; ks++) {
            // gate row r = mt*16 + g (+8): typ = r>>3, col = r&7 = g
            size_t row0 = (size_t)((2*mt + 0)*HH + colbase + g) * HH;
            size_t row1 = (size_t)((2*mt + 1)*HH + colbase + g) * HH;
            int k = kg*64 + ks*8 + tg;
            a[mt][ks][0] = f2tf32(whh[row0 + k]);
            a[mt][ks][1] = f2tf32(whh[row1 + k]);
            a[mt][ks][2] = f2tf32(whh[row0 + k + 4]);
            a[mt][ks][3] = f2tf32(whh[row1 + k + 4]);
        }

    // zero tree counters (replay-safe)
    {
        int4* cz = (int4*)g_cntT;
        int q = bx*512 + tid;
        if (q < 32768) cz[q] = make_int4(0,0,0,0);
    }
    __threadfence();
    // one-shot grid barrier (monotone generation, replay-safe)
    if (tid == 0) {
        unsigned gen = ((volatile unsigned*)&g_bargen)[0];
        if (atomicAdd(&g_barcnt, 1u) == (unsigned)(gridDim.x - 1)) {
            g_barcnt = 0u;
            __threadfence();
            atomicAdd(&g_bargen, 1u);
        } else {
            while (((volatile unsigned*)&g_bargen)[0] == gen) { }
        }
    }
    __syncthreads();

    float c = 0.f;

    for (int t = 0; t < TT; t++) {
        int tt = d ? (TT - 1 - t) : t;

        // prefetch xp (overlaps barrier wait)
        float xg0 = 0.f, xg1 = 0.f, xg2 = 0.f, xg3 = 0.f;
        if (tid < 256) {
            const float* xr = g_xp + ((size_t)(d*TT + tt) * 64 + blk) * 1024 + tid;
            xg0 = xr[0]; xg1 = xr[256]; xg2 = xr[512]; xg3 = xr[768];
        }

        float cfr[2][2][4];
#pragma unroll
        for (int mt = 0; mt < 2; mt++)
#pragma unroll
            for (int nt = 0; nt < 2; nt++)
#pragma unroll
                for (int e = 0; e < 4; e++) cfr[mt][nt][e] = 0.f;

        if (t > 0) {
            // tree barrier
            if (tid < 8) {
                const int* cp = &g_cntT[d][t-1][tid][0];
                int miss = 0;
                while (ld_acq(cp) < 8) {
                    if (++miss > 2) __nanosleep(150);
                }
            }
            __syncthreads();

            // per-warp private staging with tf32 convert (16 b-rows x 64 k)
            {
                const float* src = g_hst + (size_t)((((t+1)&1)*2 + d)*32) * 512;
#pragma unroll
                for (int i = 0; i < 8; i++) {
                    int q = i*32 + lane;
                    int row = q >> 4, k4 = (q & 15) * 4;
                    int b = 16*half + row;
                    float4 v = __ldcg((const float4*)(src + (size_t)b*512 + kg*64 + k4));
                    uint4 u = make_uint4(f2tf32(v.x), f2tf32(v.y), f2tf32(v.z), f2tf32(v.w));
                    *(uint4*)(hs + b*LP + kg*64 + k4) = u;
                }
            }
            __syncwarp();

            // 32 mma over this warp's K-slice: b-frag from hs (conflict-free)
#pragma unroll
            for (int ks = 0; ks < 8; ks++) {
                int k0 = kg*64 + ks*8;
                unsigned bfr[2][2];
#pragma unroll
                for (int nt = 0; nt < 2; nt++) {
                    const unsigned* B0 =
                        (const unsigned*)(hs + (half*16 + nt*8 + g)*LP + k0);
                    bfr[nt][0] = B0[tg]; bfr[nt][1] = B0[tg+4];
                }
#pragma unroll
                for (int mt = 0; mt < 2; mt++)
#pragma unroll
                    for (int nt = 0; nt < 2; nt++)
                        mma_tf32(cfr[mt][nt], a[mt][ks], bfr[nt]);
            }
        }
        // scatter C fragments into red[kg][typ][b][col]
#pragma unroll
        for (int mt = 0; mt < 2; mt++)
#pragma unroll
            for (int nt = 0; nt < 2; nt++)
#pragma unroll
                for (int e = 0; e < 4; e++) {
                    int typ = 2*mt + (e >> 1);
                    int b = half*16 + nt*8 + 2*tg + (e & 1);
                    red[kg*1024 + typ*256 + b*8 + g] = cfr[mt][nt][e];
                }
        __syncthreads();

        // phase 2: reduce K-groups, nonlinearity, write h (threads 0..255)
        float h = 0.f;
        if (tid < 256) {
            float s0 = xg0, s1 = xg1, s2 = xg2, s3 = xg3;
#pragma unroll
            for (int g2 = 0; g2 < 8; g2++) {
                s0 += red[g2*1024 + 0*256 + tid];
                s1 += red[g2*1024 + 1*256 + tid];
                s2 += red[g2*1024 + 2*256 + tid];
                s3 += red[g2*1024 + 3*256 + tid];
            }
            c = sigf(s1) * c + sigf(s0) * tanhf(s2);
            h = sigf(s3) * tanhf(c);
            __stcg(&g_hst[((size_t)(((t&1)*2 + d)*32) + pb)*512 + colbase + pcol], h);
        }
        __syncthreads();   // h stores happen-before tid0's release-add
        if (tid == 0) red_add_rel(&g_cntT[d][t][bx & 7][0]);
        // off critical path
        if (tid < 256)
            g_hcat[((size_t)(pb*TT + tt))*1024 + d*HH + colbase + pcol] = h;
    }
}

// ---------------- kernel 4: classifier (emissions) ---------------------------
__global__ void k_cls(const float* __restrict__ cw, const float* __restrict__ cb) {
    __shared__ float hsm[1024];
    int m = blockIdx.x;
    const float4* src = (const float4*)(g_hcat + (size_t)m * 1024);
    for (int i = threadIdx.x; i < 256; i += blockDim.x) ((float4*)hsm)[i] = src[i];
    __syncthreads();
    int w = threadIdx.x >> 5, lane = threadIdx.x & 31;
    if (w < CC) {
        const float* wr = cw + w * 1024;
        float s = 0.f;
        for (int j = lane; j < 1024; j += 32) s += hsm[j] * wr[j];
#pragma unroll
        for (int off = 16; off; off >>= 1) s += __shfl_down_sync(0xffffffffu, s, off);
        if (lane == 0) g_emis[(size_t)m * CC + w] = s + cb[w];
    }
}

// ---------------- kernel 5: CRF log-likelihood (mask all-true) ---------------
__global__ void k_crf(const int* __restrict__ label, const float* __restrict__ startv,
                      const float* __restrict__ endv, const float* __restrict__ trans) {
    int b = blockIdx.x, lane = threadIdx.x;
    const int* tg = label + b * TT;
    const float* em = g_emis + (size_t)b * TT * CC;

    float p = 0.f;
    for (int t = lane; t < TT; t += 32) {
        int tag = tg[t];
        p += em[t*CC + tag];
        if (t > 0) p += trans[tg[t-1]*CC + tag];
    }
#pragma unroll
    for (int off = 16; off; off >>= 1) p += __shfl_down_sync(0xffffffffu, p, off);
    float num = __shfl_sync(0xffffffffu, p, 0);
    num += startv[tg[0]] + endv[tg[TT-1]];

    int j = (lane < CC) ? lane : 0;
    float trc[CC];
#pragma unroll
    for (int i = 0; i < CC; i++) trc[i] = trans[i*CC + j];
    float alpha = startv[j] + em[j];
    float em_next = em[CC + j];
    for (int t = 1; t < TT; t++) {
        float a[CC];
#pragma unroll
        for (int i = 0; i < CC; i++) a[i] = __shfl_sync(0xffffffffu, alpha, i) + trc[i];
        float em_t = em_next;
        if (t < TT-1) em_next = em[(t+1)*CC + j];
        float mx = a[0];
#pragma unroll
        for (int i = 1; i < CC; i++) mx = fmaxf(mx, a[i]);
        float s = 0.f;
#pragma unroll
        for (int i = 0; i < CC; i++) s += expf(a[i] - mx);
        alpha = mx + logf(s) + em_t;
    }
    float v = alpha + endv[j];
    float mv = v;
#pragma unroll
    for (int i = 0; i < CC; i++) mv = fmaxf(mv, __shfl_sync(0xffffffffu, v, i));
    float se = expf(v - mv);
    float tot = 0.f;
#pragma unroll
    for (int i = 0; i < CC; i++) tot += __shfl_sync(0xffffffffu, se, i);
    float den = mv + logf(tot);
    if (lane == 0) g_llh[b] = num - den;
}

// ---------------- kernel 6: final reduction ----------------------------------
__global__ void k_final(float* out) {
    if (threadIdx.x == 0) {
        float s = 0.f;
        for (int i = 0; i < BB; i++) s += g_llh[i];
        out[0] = -s / (float)BB;
    }
}

// ---------------- launch ------------------------------------------------------
extern "C" void kernel_launch(void* const* d_in, const int* in_sizes, int n_in,
                              void* d_out, int out_size) {
    const int*   input  = (const int*)d_in[0];
    const int*   label  = (const int*)d_in[1];
    const float* emb    = (const float*)d_in[2];
    const float* w_ih_f = (const float*)d_in[3];
    const float* w_hh_f = (const float*)d_in[4];
    const float* b_ih_f = (const float*)d_in[5];
    const float* b_hh_f = (const float*)d_in[6];
    const float* w_ih_b = (const float*)d_in[7];
    const float* w_hh_b = (const float*)d_in[8];
    const float* b_ih_b = (const float*)d_in[9];
    const float* b_hh_b = (const float*)d_in[10];
    const float* cls_w  = (const float*)d_in[11];
    const float* cls_b  = (const float*)d_in[12];
    const float* startv = (const float*)d_in[13];
    const float* endv   = (const float*)d_in[14];
    const float* trans  = (const float*)d_in[15];

    cudaFuncSetAttribute(k_lstm, cudaFuncAttributeMaxDynamicSharedMemorySize, LSTM_SMEM_BYTES);

    k_gather<<<MTOT, 128>>>(input, emb);
    k_xpgemm_tc<<<dim3(32, 64), 256>>>(w_ih_f, w_ih_b, b_ih_f, b_hh_f, b_ih_b, b_hh_b);
    k_dummy<<<1, 32>>>();   // keeps ncu window on k_lstm
    k_lstm<<<LSTM_BLOCKS, 512, LSTM_SMEM_BYTES>>>(w_hh_f, w_hh_b);
    k_cls<<<MTOT, 288>>>(cls_w, cls_b);
    k_crf<<<BB, 32>>>(label, startv, endv, trans);
    k_final<<<1, 32>>>((float*)d_out);
}

// round 15
// speedup vs baseline: 2.7632x; 1.3769x over previous
#include <cuda_runtime.h>
#include <cuda_bf16.h>
#include <math.h>

// Problem dims
#define BB 32
#define TT 256
#define EE 512
#define HH 512
#define GG 2048   // 4*H
#define CC 9
#define MTOT (BB*TT)          // 8192
#define LSTM_BLOCKS 128       // 64 per direction
#define LP 516                // padded pitch (words) for hs rows
#define LSTM_SMEM_FLOATS (32*LP + 8192 + 32)
#define LSTM_SMEM_BYTES (LSTM_SMEM_FLOATS*4)
#define XP 36                 // xpgemm smem pitch
#define XSZ (128*XP)
#define XPG_SMEM_BYTES (4*XSZ*4)   // 2 bufs x (A,B)

// ---------------- device scratch (static, no runtime allocation) -------------
__device__ float g_x[MTOT*EE];                 // gathered embeddings [m][512]
__device__ float g_xp[2L*TT*BB*GG];            // [d][t][blk(64)][typ(4)][b(32)][col(8)]
__device__ float g_hcat[(size_t)MTOT*1024];    // [b*256+t][hf(512)|hb(512)]
__device__ float g_hst[2*2*BB*HH];             // [par][dir][b][k]  double buffer
__device__ float g_emis[MTOT*CC];              // [b*256+t][9]
__device__ float g_llh[BB];
__device__ int   g_cntT[2][TT][8][32];         // tree counters, 1 line each
__device__ unsigned g_barcnt;                  // zero-initialized at load
__device__ unsigned g_bargen;
__device__ int   g_dummy_sink;

__device__ __forceinline__ int ld_acq(const int* p) {
    int v;
    asm volatile("ld.acquire.gpu.global.b32 %0, [%1];" : "=r"(v) : "l"(p));
    return v;
}
__device__ __forceinline__ void red_add_rel(int* p) {
    asm volatile("red.release.gpu.global.add.s32 [%0], %1;" :: "l"(p), "r"(1) : "memory");
}
__device__ __forceinline__ int ld_acq_cta(const int* p) {
    int v;
    asm volatile("ld.acquire.cta.b32 %0, [%1];" : "=r"(v) : "l"(p) : "memory");
    return v;
}
__device__ __forceinline__ void st_rel_cta(int* p, int v) {
    asm volatile("st.release.cta.b32 [%0], %1;" :: "l"(p), "r"(v) : "memory");
}
__device__ __forceinline__ void cp16(float* smem_dst, const float* gsrc) {
    unsigned sa = (unsigned)__cvta_generic_to_shared(smem_dst);
    asm volatile("cp.async.cg.shared.global [%0], [%1], 16;" :: "r"(sa), "l"(gsrc));
}
__device__ __forceinline__ unsigned f2tf32(float f) {
    unsigned u;
    asm("cvt.rna.tf32.f32 %0, %1;" : "=r"(u) : "f"(f));
    return u;
}
__device__ __forceinline__ void mma_tf32(float* d, const unsigned* a, const unsigned* b) {
    asm("mma.sync.aligned.m16n8k8.row.col.f32.tf32.tf32.f32 "
        "{%0,%1,%2,%3}, {%4,%5,%6,%7}, {%8,%9}, {%0,%1,%2,%3};"
        : "+f"(d[0]), "+f"(d[1]), "+f"(d[2]), "+f"(d[3])
        : "r"(a[0]), "r"(a[1]), "r"(a[2]), "r"(a[3]), "r"(b[0]), "r"(b[1]));
}

// ---------------- kernel 1: embedding gather (zero row 0) --------------------
__global__ void k_gather(const int* __restrict__ inp, const float* __restrict__ emb) {
    int m = blockIdx.x;
    int tok = inp[m];
    float4* dst = (float4*)(g_x + (size_t)m * EE);
    if (tok == 0) {
        float4 z = make_float4(0.f, 0.f, 0.f, 0.f);
        for (int i = threadIdx.x; i < EE/4; i += blockDim.x) dst[i] = z;
    } else {
        const float4* src = (const float4*)(emb + (size_t)tok * EE);
        for (int i = threadIdx.x; i < EE/4; i += blockDim.x) dst[i] = src[i];
    }
}

// ---------------- kernel 2: xp GEMM (tf32 tensor, cp.async double-buffer) ----
__global__ __launch_bounds__(256, 2) void k_xpgemm_tc(
    const float* __restrict__ wf, const float* __restrict__ wb,
    const float* __restrict__ bihf, const float* __restrict__ bhhf,
    const float* __restrict__ bihb, const float* __restrict__ bhhb)
{
    extern __shared__ float xsm[];
    float* AS = xsm;            // [2][XSZ]
    float* BS = xsm + 2*XSZ;    // [2][XSZ]

    int ntile = blockIdx.x;            // 0..31 over 4096 cols
    int m0 = blockIdx.y * 128;
    int dir = (ntile >= 16) ? 1 : 0;
    int nloc0 = (ntile & 15) * 128;
    const float* w   = dir ? wb : wf;
    const float* bih = dir ? bihb : bihf;
    const float* bhh = dir ? bhhb : bhhf;

    int tid = threadIdx.x;
    int lane = tid & 31;
    int wr = tid >> 5;                 // warp 0..7
    int wm = wr >> 1, wn = wr & 1;     // warp grid 4x2
    int g = lane >> 2, tg = lane & 3;  // groupID, threadID-in-group
    int srow = tid >> 1, skq = (tid & 1) * 16;

    float c[2][8][4];
#pragma unroll
    for (int mt = 0; mt < 2; mt++)
#pragma unroll
        for (int nt = 0; nt < 8; nt++)
#pragma unroll
            for (int e = 0; e < 4; e++) c[mt][nt][e] = 0.f;

    // raw fp32 bits staged; mma consumes as tf32 (HW truncation)
    const float* axb = g_x + (size_t)(m0 + srow) * EE + skq;
    const float* bxb = w   + (size_t)(nloc0 + srow) * EE + skq;

    // prologue: stage kt=0 into buf0
    {
        float* ad = AS + srow*XP + skq;
        float* bd = BS + srow*XP + skq;
#pragma unroll
        for (int i = 0; i < 4; i++) { cp16(ad + i*4, axb + i*4); cp16(bd + i*4, bxb + i*4); }
        asm volatile("cp.async.commit_group;");
    }

    for (int ktI = 0; ktI < 16; ktI++) {
        if (ktI < 15) {
            int buf = (ktI + 1) & 1;
            int kt = (ktI + 1) * 32;
            float* ad = AS + buf*XSZ + srow*XP + skq;
            float* bd = BS + buf*XSZ + srow*XP + skq;
#pragma unroll
            for (int i = 0; i < 4; i++) { cp16(ad + i*4, axb + kt + i*4); cp16(bd + i*4, bxb + kt + i*4); }
            asm volatile("cp.async.commit_group;");
            asm volatile("cp.async.wait_group 1;");
        } else {
            asm volatile("cp.async.wait_group 0;");
        }
        __syncthreads();

        const float* Ab = AS + (ktI & 1)*XSZ;
        const float* Bb = BS + (ktI & 1)*XSZ;
#pragma unroll
        for (int ks = 0; ks < 4; ks++) {
            int kk = ks * 8;
            unsigned a[2][4];
#pragma unroll
            for (int mt = 0; mt < 2; mt++) {
                int rm = wm*32 + mt*16;
                const unsigned* A0 = (const unsigned*)(Ab + (rm + g)*XP + kk);
                const unsigned* A8 = (const unsigned*)(Ab + (rm + g + 8)*XP + kk);
                a[mt][0] = A0[tg];   a[mt][1] = A8[tg];
                a[mt][2] = A0[tg+4]; a[mt][3] = A8[tg+4];
            }
#pragma unroll
            for (int nt = 0; nt < 8; nt++) {
                int cn = wn*64 + nt*8;
                const unsigned* B0 = (const unsigned*)(Bb + (cn + g)*XP + kk);
                unsigned b[2];
                b[0] = B0[tg]; b[1] = B0[tg+4];
                mma_tf32(c[0][nt], a[0], b);
                mma_tf32(c[1][nt], a[1], b);
            }
        }
        __syncthreads();
    }

    float biasv[16];
#pragma unroll
    for (int nt = 0; nt < 8; nt++)
#pragma unroll
        for (int e = 0; e < 2; e++) {
            int g0 = nloc0 + wn*64 + nt*8 + 2*tg + e;
            biasv[nt*2+e] = bih[g0] + bhh[g0];
        }

#pragma unroll
    for (int mt = 0; mt < 2; mt++)
#pragma unroll
        for (int rh = 0; rh < 2; rh++) {
            int m = m0 + wm*32 + mt*16 + g + rh*8;
            int bidx = m >> 8, t = m & 255;
            size_t tb = ((size_t)(dir*TT + t) * 64);
#pragma unroll
            for (int nt = 0; nt < 8; nt++)
#pragma unroll
                for (int e = 0; e < 2; e++) {
                    int g0 = nloc0 + wn*64 + nt*8 + 2*tg + e;
                    int typ = g0 >> 9, c9 = g0 & 511;
                    g_xp[(tb + (c9 >> 3)) * 1024 + typ*256 + bidx*8 + (c9 & 7)]
                        = c[mt][nt][rh*2 + e] + biasv[nt*2+e];
                }
        }
}

// ---------------- dummy kernel (keeps ncu -s window on k_lstm) ---------------
__global__ void k_dummy() { if (threadIdx.x == 1234567) g_dummy_sink = 1; }

// ---------------- kernel 3: persistent bidirectional LSTM (tf32 tensor) ------
// Chain-optimized: dedicated detector warp (15) + smem-flag broadcast (no
// block-wide barrier for detection), split bar.arrive/bar.sync exchange,
// cp.async h staging, raw-bit tf32.
__device__ __forceinline__ float sigf(float x) { return 1.f / (1.f + __expf(-x)); }

__global__ __launch_bounds__(512, 1) void k_lstm(
    const float* __restrict__ whhf, const float* __restrict__ whhb)
{
    extern __shared__ float sm[];
    float* hs   = sm;              // [32][LP]  b-major staged h (fp32 bits)
    float* red  = sm + 32*LP;      // [8 kg][4 typ][32 b][8 col]
    int*   flag = (int*)(sm + 32*LP + 8192);

    int bx = blockIdx.x;
    int d = bx >> 6;                   // direction
    int blk = bx & 63;
    int colbase = blk * 8;
    int tid = threadIdx.x;
    const float* whh = d ? whhb : whhf;

    int lane = tid & 31;
    int w = tid >> 5;
    int kg = w & 7;                    // k-slice [kg*64, kg*64+64)
    int half = w >> 3;                 // batches [16*half, 16*half+16)
    int g = lane >> 2, tg = lane & 3;  // mma groupID / thread-in-group
    int pcol = tid & 7, pb = tid >> 3; // phase-2 cell (tid<256)

    // resident W fragments: a[mt][ks][4] (rna-converted once)
    unsigned a[2][8][4];
#pragma unroll
    for (int mt = 0; mt < 2; mt++)
#pragma unroll
        for (int ks = 0; ks < 8; ks++) {
            size_t row0 = (size_t)((2*mt + 0)*HH + colbase + g) * HH;
            size_t row1 = (size_t)((2*mt + 1)*HH + colbase + g) * HH;
            int k = kg*64 + ks*8 + tg;
            a[mt][ks][0] = f2tf32(whh[row0 + k]);
            a[mt][ks][1] = f2tf32(whh[row1 + k]);
            a[mt][ks][2] = f2tf32(whh[row0 + k + 4]);
            a[mt][ks][3] = f2tf32(whh[row1 + k + 4]);
        }

    if (tid == 0) *flag = 0;
    // zero tree counters (replay-safe)
    {
        int4* cz = (int4*)g_cntT;
        int q = bx*512 + tid;
        if (q < 32768) cz[q] = make_int4(0,0,0,0);
    }
    __threadfence();
    // one-shot grid barrier (monotone generation, replay-safe)
    if (tid == 0) {
        unsigned gen = ((volatile unsigned*)&g_bargen)[0];
        if (atomicAdd(&g_barcnt, 1u) == (unsigned)(gridDim.x - 1)) {
            g_barcnt = 0u;
            __threadfence();
            atomicAdd(&g_bargen, 1u);
        } else {
            while (((volatile unsigned*)&g_bargen)[0] == gen) { }
        }
    }
    __syncthreads();

    float c = 0.f;

    for (int t = 0; t < TT; t++) {
        int tt = d ? (TT - 1 - t) : t;

        // prefetch xp (phase-2 warps only; overlaps waiting)
        float xg0 = 0.f, xg1 = 0.f, xg2 = 0.f, xg3 = 0.f;
        if (tid < 256) {
            const float* xr = g_xp + ((size_t)(d*TT + tt) * 64 + blk) * 1024 + tid;
            xg0 = xr[0]; xg1 = xr[256]; xg2 = xr[512]; xg3 = xr[768];
        }

        float cfr[2][2][4];
#pragma unroll
        for (int mt = 0; mt < 2; mt++)
#pragma unroll
            for (int nt = 0; nt < 2; nt++)
#pragma unroll
                for (int e = 0; e < 4; e++) cfr[mt][nt][e] = 0.f;

        if (t > 0) {
            // detection: warp 15 polls global counters, broadcasts via smem flag
            if (w == 15) {
                if (lane < 8) {
                    const int* cp = &g_cntT[d][t-1][lane][0];
                    int miss = 0;
                    while (ld_acq(cp) < 8) {
                        if (++miss > 4) __nanosleep(40);
                    }
                }
                __syncwarp();
                if (lane == 0) st_rel_cta(flag, t);
            } else {
                if (lane == 0) { while (ld_acq_cta(flag) < t) { } }
                __syncwarp();
            }

            // per-warp private h staging via cp.async.cg (L2-coherent)
            {
                const float* src = g_hst + (size_t)((((t+1)&1)*2 + d)*32) * 512;
#pragma unroll
                for (int i = 0; i < 8; i++) {
                    int q = i*32 + lane;
                    int row = q >> 4, k4 = (q & 15) * 4;
                    int b = 16*half + row;
                    cp16(hs + b*LP + kg*64 + k4, src + (size_t)b*512 + kg*64 + k4);
                }
                asm volatile("cp.async.commit_group;");
                asm volatile("cp.async.wait_group 0;");
            }
            __syncwarp();

            // 32 mma over this warp's K-slice (raw fp32 bits as tf32)
#pragma unroll
            for (int ks = 0; ks < 8; ks++) {
                int k0 = kg*64 + ks*8;
                unsigned bfr[2][2];
#pragma unroll
                for (int nt = 0; nt < 2; nt++) {
                    const unsigned* B0 =
                        (const unsigned*)(hs + (half*16 + nt*8 + g)*LP + k0);
                    bfr[nt][0] = B0[tg]; bfr[nt][1] = B0[tg+4];
                }
#pragma unroll
                for (int mt = 0; mt < 2; mt++)
#pragma unroll
                    for (int nt = 0; nt < 2; nt++)
                        mma_tf32(cfr[mt][nt], a[mt][ks], bfr[nt]);
            }
        }
        // scatter C fragments into red[kg][typ][b][col]
#pragma unroll
        for (int mt = 0; mt < 2; mt++)
#pragma unroll
            for (int nt = 0; nt < 2; nt++)
#pragma unroll
                for (int e = 0; e < 4; e++) {
                    int typ = 2*mt + (e >> 1);
                    int b = half*16 + nt*8 + 2*tg + (e & 1);
                    red[kg*1024 + typ*256 + b*8 + g] = cfr[mt][nt][e];
                }
        // split exchange barrier: producers (warps 8-15) don't block
        if (w < 8) {
            asm volatile("bar.sync 3, 512;" ::: "memory");
        } else {
            asm volatile("bar.arrive 3, 512;" ::: "memory");
        }

        // phase 2 (warps 0-7): reduce K-groups, nonlinearity, write h
        float h = 0.f;
        if (tid < 256) {
            float s0 = xg0, s1 = xg1, s2 = xg2, s3 = xg3;
#pragma unroll
            for (int g2 = 0; g2 < 8; g2++) {
                s0 += red[g2*1024 + 0*256 + tid];
                s1 += red[g2*1024 + 1*256 + tid];
                s2 += red[g2*1024 + 2*256 + tid];
                s3 += red[g2*1024 + 3*256 + tid];
            }
            c = sigf(s1) * c + sigf(s0) * tanhf(s2);
            h = sigf(s3) * tanhf(c);
            __stcg(&g_hst[((size_t)(((t&1)*2 + d)*32) + pb)*512 + colbase + pcol], h);
            asm volatile("bar.sync 1, 256;" ::: "memory");
            if (tid == 0) red_add_rel(&g_cntT[d][t][bx & 7][0]);
            // off critical path
            g_hcat[((size_t)(pb*TT + tt))*1024 + d*HH + colbase + pcol] = h;
        }
    }
}

// ---------------- kernel 4: classifier (emissions) ---------------------------
__global__ void k_cls(const float* __restrict__ cw, const float* __restrict__ cb) {
    __shared__ float hsm[1024];
    int m = blockIdx.x;
    const float4* src = (const float4*)(g_hcat + (size_t)m * 1024);
    for (int i = threadIdx.x; i < 256; i += blockDim.x) ((float4*)hsm)[i] = src[i];
    __syncthreads();
    int w = threadIdx.x >> 5, lane = threadIdx.x & 31;
    if (w < CC) {
        const float* wr = cw + w * 1024;
        float s = 0.f;
        for (int j = lane; j < 1024; j += 32) s += hsm[j] * wr[j];
#pragma unroll
        for (int off = 16; off; off >>= 1) s += __shfl_down_sync(0xffffffffu, s, off);
        if (lane == 0) g_emis[(size_t)m * CC + w] = s + cb[w];
    }
}

// ---------------- kernel 5: CRF log-likelihood (mask all-true) ---------------
__global__ void k_crf(const int* __restrict__ label, const float* __restrict__ startv,
                      const float* __restrict__ endv, const float* __restrict__ trans) {
    int b = blockIdx.x, lane = threadIdx.x;
    const int* tg = label + b * TT;
    const float* em = g_emis + (size_t)b * TT * CC;

    float p = 0.f;
    for (int t = lane; t < TT; t += 32) {
        int tag = tg[t];
        p += em[t*CC + tag];
        if (t > 0) p += trans[tg[t-1]*CC + tag];
    }
#pragma unroll
    for (int off = 16; off; off >>= 1) p += __shfl_down_sync(0xffffffffu, p, off);
    float num = __shfl_sync(0xffffffffu, p, 0);
    num += startv[tg[0]] + endv[tg[TT-1]];

    int j = (lane < CC) ? lane : 0;
    float trc[CC];
#pragma unroll
    for (int i = 0; i < CC; i++) trc[i] = trans[i*CC + j];
    float alpha = startv[j] + em[j];
    float em_next = em[CC + j];
    for (int t = 1; t < TT; t++) {
        float a[CC];
#pragma unroll
        for (int i = 0; i < CC; i++) a[i] = __shfl_sync(0xffffffffu, alpha, i) + trc[i];
        float em_t = em_next;
        if (t < TT-1) em_next = em[(t+1)*CC + j];
        float mx = a[0];
#pragma unroll
        for (int i = 1; i < CC; i++) mx = fmaxf(mx, a[i]);
        float s = 0.f;
#pragma unroll
        for (int i = 0; i < CC; i++) s += expf(a[i] - mx);
        alpha = mx + logf(s) + em_t;
    }
    float v = alpha + endv[j];
    float mv = v;
#pragma unroll
    for (int i = 0; i < CC; i++) mv = fmaxf(mv, __shfl_sync(0xffffffffu, v, i));
    float se = expf(v - mv);
    float tot = 0.f;
#pragma unroll
    for (int i = 0; i < CC; i++) tot += __shfl_sync(0xffffffffu, se, i);
    float den = mv + logf(tot);
    if (lane == 0) g_llh[b] = num - den;
}

// ---------------- kernel 6: final reduction ----------------------------------
__global__ void k_final(float* out) {
    if (threadIdx.x == 0) {
        float s = 0.f;
        for (int i = 0; i < BB; i++) s += g_llh[i];
        out[0] = -s / (float)BB;
    }
}

// ---------------- launch ------------------------------------------------------
extern "C" void kernel_launch(void* const* d_in, const int* in_sizes, int n_in,
                              void* d_out, int out_size) {
    const int*   input  = (const int*)d_in[0];
    const int*   label  = (const int*)d_in[1];
    const float* emb    = (const float*)d_in[2];
    const float* w_ih_f = (const float*)d_in[3];
    const float* w_hh_f = (const float*)d_in[4];
    const float* b_ih_f = (const float*)d_in[5];
    const float* b_hh_f = (const float*)d_in[6];
    const float* w_ih_b = (const float*)d_in[7];
    const float* w_hh_b = (const float*)d_in[8];
    const float* b_ih_b = (const float*)d_in[9];
    const float* b_hh_b = (const float*)d_in[10];
    const float* cls_w  = (const float*)d_in[11];
    const float* cls_b  = (const float*)d_in[12];
    const float* startv = (const float*)d_in[13];
    const float* endv   = (const float*)d_in[14];
    const float* trans  = (const float*)d_in[15];

    cudaFuncSetAttribute(k_lstm, cudaFuncAttributeMaxDynamicSharedMemorySize, LSTM_SMEM_BYTES);
    cudaFuncSetAttribute(k_xpgemm_tc, cudaFuncAttributeMaxDynamicSharedMemorySize, XPG_SMEM_BYTES);

    k_gather<<<MTOT, 128>>>(input, emb);
    k_xpgemm_tc<<<dim3(32, 64), 256, XPG_SMEM_BYTES>>>(w_ih_f, w_ih_b, b_ih_f, b_hh_f, b_ih_b, b_hh_b);
    k_dummy<<<1, 32>>>();   // keeps ncu window on k_lstm
    k_lstm<<<LSTM_BLOCKS, 512, LSTM_SMEM_BYTES>>>(w_hh_f, w_hh_b);
    k_cls<<<MTOT, 288>>>(cls_w, cls_b);
    k_crf<<<BB, 32>>>(label, startv, endv, trans);
    k_final<<<1, 32>>>((float*)d_out);
}

// round 16
// speedup vs baseline: 2.8379x; 1.0270x over previous
#include <cuda_runtime.h>
#include <cuda_bf16.h>
#include <math.h>

// Problem dims
#define BB 32
#define TT 256
#define EE 512
#define HH 512
#define GG 2048   // 4*H
#define CC 9
#define MTOT (BB*TT)          // 8192
#define LSTM_BLOCKS 128       // 64 per direction
#define LP 516                // padded pitch (words) for hs rows
#define LSTM_SMEM_FLOATS (32*LP + 8192 + 32)
#define LSTM_SMEM_BYTES (LSTM_SMEM_FLOATS*4)
#define XP 36                 // xpgemm smem pitch
#define XSZ (128*XP)
#define XPG_SMEM_BYTES (4*XSZ*4)   // 2 bufs x (A,B)

// ---------------- device scratch (static, no runtime allocation) -------------
__device__ float g_x[MTOT*EE];                 // gathered embeddings [m][512]
__device__ float g_xp[2L*TT*BB*GG];            // [d][t][blk(64)][typ(4)][b(32)][col(8)]
__device__ float g_hcat[(size_t)MTOT*1024];    // [b*256+t][hf(512)|hb(512)]
__device__ float g_hst[2*2*BB*HH];             // [par][dir][b][k]  double buffer
__device__ float g_emis[MTOT*CC];              // [b*256+t][9]
__device__ float g_llh[BB];
__device__ int   g_cntT[2][TT][8][32];         // slice counters, 1 line each
__device__ unsigned g_barcnt;                  // zero-initialized at load
__device__ unsigned g_bargen;
__device__ int   g_dummy_sink;

__device__ __forceinline__ int ld_acq(const int* p) {
    int v;
    asm volatile("ld.acquire.gpu.global.b32 %0, [%1];" : "=r"(v) : "l"(p));
    return v;
}
__device__ __forceinline__ void red_add_rel(int* p) {
    asm volatile("red.release.gpu.global.add.s32 [%0], %1;" :: "l"(p), "r"(1) : "memory");
}
__device__ __forceinline__ int ld_acq_cta(const int* p) {
    int v;
    asm volatile("ld.acquire.cta.b32 %0, [%1];" : "=r"(v) : "l"(p) : "memory");
    return v;
}
__device__ __forceinline__ void red_add_rel_cta(int* p) {
    asm volatile("red.release.cta.add.s32 [%0], %1;" :: "l"(p), "r"(1) : "memory");
}
__device__ __forceinline__ void cp16(float* smem_dst, const float* gsrc) {
    unsigned sa = (unsigned)__cvta_generic_to_shared(smem_dst);
    asm volatile("cp.async.cg.shared.global [%0], [%1], 16;" :: "r"(sa), "l"(gsrc));
}
__device__ __forceinline__ unsigned f2tf32(float f) {
    unsigned u;
    asm("cvt.rna.tf32.f32 %0, %1;" : "=r"(u) : "f"(f));
    return u;
}
__device__ __forceinline__ void mma_tf32(float* d, const unsigned* a, const unsigned* b) {
    asm("mma.sync.aligned.m16n8k8.row.col.f32.tf32.tf32.f32 "
        "{%0,%1,%2,%3}, {%4,%5,%6,%7}, {%8,%9}, {%0,%1,%2,%3};"
        : "+f"(d[0]), "+f"(d[1]), "+f"(d[2]), "+f"(d[3])
        : "r"(a[0]), "r"(a[1]), "r"(a[2]), "r"(a[3]), "r"(b[0]), "r"(b[1]));
}

// ---------------- kernel 1: embedding gather (zero row 0) --------------------
__global__ void k_gather(const int* __restrict__ inp, const float* __restrict__ emb) {
    int m = blockIdx.x;
    int tok = inp[m];
    float4* dst = (float4*)(g_x + (size_t)m * EE);
    if (tok == 0) {
        float4 z = make_float4(0.f, 0.f, 0.f, 0.f);
        for (int i = threadIdx.x; i < EE/4; i += blockDim.x) dst[i] = z;
    } else {
        const float4* src = (const float4*)(emb + (size_t)tok * EE);
        for (int i = threadIdx.x; i < EE/4; i += blockDim.x) dst[i] = src[i];
    }
}

// ---------------- kernel 2: xp GEMM (tf32 tensor, cp.async double-buffer) ----
__global__ __launch_bounds__(256, 2) void k_xpgemm_tc(
    const float* __restrict__ wf, const float* __restrict__ wb,
    const float* __restrict__ bihf, const float* __restrict__ bhhf,
    const float* __restrict__ bihb, const float* __restrict__ bhhb)
{
    extern __shared__ float xsm[];
    float* AS = xsm;            // [2][XSZ]
    float* BS = xsm + 2*XSZ;    // [2][XSZ]

    int ntile = blockIdx.x;            // 0..31 over 4096 cols
    int m0 = blockIdx.y * 128;
    int dir = (ntile >= 16) ? 1 : 0;
    int nloc0 = (ntile & 15) * 128;
    const float* w   = dir ? wb : wf;
    const float* bih = dir ? bihb : bihf;
    const float* bhh = dir ? bhhb : bhhf;

    int tid = threadIdx.x;
    int lane = tid & 31;
    int wr = tid >> 5;                 // warp 0..7
    int wm = wr >> 1, wn = wr & 1;     // warp grid 4x2
    int g = lane >> 2, tg = lane & 3;  // groupID, threadID-in-group
    int srow = tid >> 1, skq = (tid & 1) * 16;

    float c[2][8][4];
#pragma unroll
    for (int mt = 0; mt < 2; mt++)
#pragma unroll
        for (int nt = 0; nt < 8; nt++)
#pragma unroll
            for (int e = 0; e < 4; e++) c[mt][nt][e] = 0.f;

    const float* axb = g_x + (size_t)(m0 + srow) * EE + skq;
    const float* bxb = w   + (size_t)(nloc0 + srow) * EE + skq;

    {
        float* ad = AS + srow*XP + skq;
        float* bd = BS + srow*XP + skq;
#pragma unroll
        for (int i = 0; i < 4; i++) { cp16(ad + i*4, axb + i*4); cp16(bd + i*4, bxb + i*4); }
        asm volatile("cp.async.commit_group;");
    }

    for (int ktI = 0; ktI < 16; ktI++) {
        if (ktI < 15) {
            int buf = (ktI + 1) & 1;
            int kt = (ktI + 1) * 32;
            float* ad = AS + buf*XSZ + srow*XP + skq;
            float* bd = BS + buf*XSZ + srow*XP + skq;
#pragma unroll
            for (int i = 0; i < 4; i++) { cp16(ad + i*4, axb + kt + i*4); cp16(bd + i*4, bxb + kt + i*4); }
            asm volatile("cp.async.commit_group;");
            asm volatile("cp.async.wait_group 1;");
        } else {
            asm volatile("cp.async.wait_group 0;");
        }
        __syncthreads();

        const float* Ab = AS + (ktI & 1)*XSZ;
        const float* Bb = BS + (ktI & 1)*XSZ;
#pragma unroll
        for (int ks = 0; ks < 4; ks++) {
            int kk = ks * 8;
            unsigned a[2][4];
#pragma unroll
            for (int mt = 0; mt < 2; mt++) {
                int rm = wm*32 + mt*16;
                const unsigned* A0 = (const unsigned*)(Ab + (rm + g)*XP + kk);
                const unsigned* A8 = (const unsigned*)(Ab + (rm + g + 8)*XP + kk);
                a[mt][0] = A0[tg];   a[mt][1] = A8[tg];
                a[mt][2] = A0[tg+4]; a[mt][3] = A8[tg+4];
            }
#pragma unroll
            for (int nt = 0; nt < 8; nt++) {
                int cn = wn*64 + nt*8;
                const unsigned* B0 = (const unsigned*)(Bb + (cn + g)*XP + kk);
                unsigned b[2];
                b[0] = B0[tg]; b[1] = B0[tg+4];
                mma_tf32(c[0][nt], a[0], b);
                mma_tf32(c[1][nt], a[1], b);
            }
        }
        __syncthreads();
    }

    float biasv[16];
#pragma unroll
    for (int nt = 0; nt < 8; nt++)
#pragma unroll
        for (int e = 0; e < 2; e++) {
            int g0 = nloc0 + wn*64 + nt*8 + 2*tg + e;
            biasv[nt*2+e] = bih[g0] + bhh[g0];
        }

#pragma unroll
    for (int mt = 0; mt < 2; mt++)
#pragma unroll
        for (int rh = 0; rh < 2; rh++) {
            int m = m0 + wm*32 + mt*16 + g + rh*8;
            int bidx = m >> 8, t = m & 255;
            size_t tb = ((size_t)(dir*TT + t) * 64);
#pragma unroll
            for (int nt = 0; nt < 8; nt++)
#pragma unroll
                for (int e = 0; e < 2; e++) {
                    int g0 = nloc0 + wn*64 + nt*8 + 2*tg + e;
                    int typ = g0 >> 9, c9 = g0 & 511;
                    g_xp[(tb + (c9 >> 3)) * 1024 + typ*256 + bidx*8 + (c9 & 7)]
                        = c[mt][nt][rh*2 + e] + biasv[nt*2+e];
                }
        }
}

// ---------------- dummy kernel (keeps ncu -s window on k_lstm) ---------------
__global__ void k_dummy() { if (threadIdx.x == 1234567) g_dummy_sink = 1; }

// ---------------- kernel 3: persistent bidirectional LSTM (tf32 tensor) ------
// Slice-local waits: warp kg polls ONLY counter kg (64 warp-granular releases
// from its 8 producer blocks). No detector warp, no flag, no bar1. red WAR
// protected by cta-scope smem gate; bar3 reassembles the global gate.
__device__ __forceinline__ float sigf(float x) { return 1.f / (1.f + __expf(-x)); }

__global__ __launch_bounds__(512, 1) void k_lstm(
    const float* __restrict__ whhf, const float* __restrict__ whhb)
{
    extern __shared__ float sm[];
    float* hs   = sm;              // [32][LP]  b-major staged h (fp32 bits)
    float* red  = sm + 32*LP;      // [8 kg][4 typ][32 b][8 col]
    int*   p2c  = (int*)(sm + 32*LP + 8192);   // phase-2 completion counter

    int bx = blockIdx.x;
    int d = bx >> 6;                   // direction
    int blk = bx & 63;
    int colbase = blk * 8;
    int tid = threadIdx.x;
    const float* whh = d ? whhb : whhf;

    int lane = tid & 31;
    int w = tid >> 5;
    int kg = w & 7;                    // k-slice [kg*64, kg*64+64)
    int half = w >> 3;                 // batches [16*half, 16*half+16)
    int g = lane >> 2, tg = lane & 3;  // mma groupID / thread-in-group
    int pcol = tid & 7, pb = tid >> 3; // phase-2 cell (tid<256)

    // resident W fragments: a[mt][ks][4] (rna-converted once)
    unsigned a[2][8][4];
#pragma unroll
    for (int mt = 0; mt < 2; mt++)
#pragma unroll
        for (int ks = 0; ks < 8; ks++) {
            size_t row0 = (size_t)((2*mt + 0)*HH + colbase + g) * HH;
            size_t row1 = (size_t)((2*mt + 1)*HH + colbase + g) * HH;
            int k = kg*64 + ks*8 + tg;
            a[mt][ks][0] = f2tf32(whh[row0 + k]);
            a[mt][ks][1] = f2tf32(whh[row1 + k]);
            a[mt][ks][2] = f2tf32(whh[row0 + k + 4]);
            a[mt][ks][3] = f2tf32(whh[row1 + k + 4]);
        }

    if (tid == 0) *p2c = 0;
    // zero slice counters (replay-safe)
    {
        int4* cz = (int4*)g_cntT;
        int q = bx*512 + tid;
        if (q < 32768) cz[q] = make_int4(0,0,0,0);
    }
    __threadfence();
    // one-shot grid barrier (monotone generation, replay-safe)
    if (tid == 0) {
        unsigned gen = ((volatile unsigned*)&g_bargen)[0];
        if (atomicAdd(&g_barcnt, 1u) == (unsigned)(gridDim.x - 1)) {
            g_barcnt = 0u;
            __threadfence();
            atomicAdd(&g_bargen, 1u);
        } else {
            while (((volatile unsigned*)&g_bargen)[0] == gen) { }
        }
    }
    __syncthreads();

    float c = 0.f;

    for (int t = 0; t < TT; t++) {
        int tt = d ? (TT - 1 - t) : t;

        // prefetch xp (phase-2 warps only; overlaps waiting)
        float xg0 = 0.f, xg1 = 0.f, xg2 = 0.f, xg3 = 0.f;
        if (tid < 256) {
            const float* xr = g_xp + ((size_t)(d*TT + tt) * 64 + blk) * 1024 + tid;
            xg0 = xr[0]; xg1 = xr[256]; xg2 = xr[512]; xg3 = xr[768];
        }

        float cfr[2][2][4];
#pragma unroll
        for (int mt = 0; mt < 2; mt++)
#pragma unroll
            for (int nt = 0; nt < 2; nt++)
#pragma unroll
                for (int e = 0; e < 4; e++) cfr[mt][nt][e] = 0.f;

        if (t > 0) {
            // slice-local wait: 64 warp-granular releases for slice kg at t-1
            if (lane == 0) {
                const int* cp = &g_cntT[d][t-1][kg][0];
                int miss = 0;
                while (ld_acq(cp) < 64) {
                    if (++miss > 4) __nanosleep(40);
                }
            }
            __syncwarp();

            // per-warp private h staging via cp.async.cg (L2-coherent)
            {
                const float* src = g_hst + (size_t)((((t+1)&1)*2 + d)*32) * 512;
#pragma unroll
                for (int i = 0; i < 8; i++) {
                    int q = i*32 + lane;
                    int row = q >> 4, k4 = (q & 15) * 4;
                    int b = 16*half + row;
                    cp16(hs + b*LP + kg*64 + k4, src + (size_t)b*512 + kg*64 + k4);
                }
                asm volatile("cp.async.commit_group;");
                asm volatile("cp.async.wait_group 0;");
            }
            __syncwarp();

            // 32 mma over this warp's K-slice (raw fp32 bits as tf32)
#pragma unroll
            for (int ks = 0; ks < 8; ks++) {
                int k0 = kg*64 + ks*8;
                unsigned bfr[2][2];
#pragma unroll
                for (int nt = 0; nt < 2; nt++) {
                    const unsigned* B0 =
                        (const unsigned*)(hs + (half*16 + nt*8 + g)*LP + k0);
                    bfr[nt][0] = B0[tg]; bfr[nt][1] = B0[tg+4];
                }
#pragma unroll
                for (int mt = 0; mt < 2; mt++)
#pragma unroll
                    for (int nt = 0; nt < 2; nt++)
                        mma_tf32(cfr[mt][nt], a[mt][ks], bfr[nt]);
            }

            // red WAR gate: phase-2 of t-1 must have finished reading red
            if (lane == 0) { while (ld_acq_cta(p2c) < 8*t) { } }
            __syncwarp();
        }
        // scatter C fragments into red[kg][typ][b][col]
#pragma unroll
        for (int mt = 0; mt < 2; mt++)
#pragma unroll
            for (int nt = 0; nt < 2; nt++)
#pragma unroll
                for (int e = 0; e < 4; e++) {
                    int typ = 2*mt + (e >> 1);
                    int b = half*16 + nt*8 + 2*tg + (e & 1);
                    red[kg*1024 + typ*256 + b*8 + g] = cfr[mt][nt][e];
                }
        // split exchange barrier: producers (warps 8-15) don't block
        if (w < 8) {
            asm volatile("bar.sync 3, 512;" ::: "memory");
        } else {
            asm volatile("bar.arrive 3, 512;" ::: "memory");
        }

        // phase 2 (warps 0-7): reduce K-groups, nonlinearity, write h,
        // per-warp release (no block barrier)
        if (tid < 256) {
            float s0 = xg0, s1 = xg1, s2 = xg2, s3 = xg3;
#pragma unroll
            for (int g2 = 0; g2 < 8; g2++) {
                s0 += red[g2*1024 + 0*256 + tid];
                s1 += red[g2*1024 + 1*256 + tid];
                s2 += red[g2*1024 + 2*256 + tid];
                s3 += red[g2*1024 + 3*256 + tid];
            }
            c = sigf(s1) * c + sigf(s0) * tanhf(s2);
            float h = sigf(s3) * tanhf(c);
            __stcg(&g_hst[((size_t)(((t&1)*2 + d)*32) + pb)*512 + colbase + pcol], h);
            __syncwarp();
            if (lane == 0) {
                red_add_rel(&g_cntT[d][t][blk >> 3][0]);  // slice-aligned
                red_add_rel_cta(p2c);                     // red-read completion
            }
            // off critical path
            g_hcat[((size_t)(pb*TT + tt))*1024 + d*HH + colbase + pcol] = h;
        }
    }
}

// ---------------- kernel 4: classifier (emissions) ---------------------------
__global__ void k_cls(const float* __restrict__ cw, const float* __restrict__ cb) {
    __shared__ float hsm[1024];
    int m = blockIdx.x;
    const float4* src = (const float4*)(g_hcat + (size_t)m * 1024);
    for (int i = threadIdx.x; i < 256; i += blockDim.x) ((float4*)hsm)[i] = src[i];
    __syncthreads();
    int w = threadIdx.x >> 5, lane = threadIdx.x & 31;
    if (w < CC) {
        const float* wr = cw + w * 1024;
        float s = 0.f;
        for (int j = lane; j < 1024; j += 32) s += hsm[j] * wr[j];
#pragma unroll
        for (int off = 16; off; off >>= 1) s += __shfl_down_sync(0xffffffffu, s, off);
        if (lane == 0) g_emis[(size_t)m * CC + w] = s + cb[w];
    }
}

// ---------------- kernel 5: CRF log-likelihood (mask all-true) ---------------
__global__ void k_crf(const int* __restrict__ label, const float* __restrict__ startv,
                      const float* __restrict__ endv, const float* __restrict__ trans) {
    int b = blockIdx.x, lane = threadIdx.x;
    const int* tg = label + b * TT;
    const float* em = g_emis + (size_t)b * TT * CC;

    float p = 0.f;
    for (int t = lane; t < TT; t += 32) {
        int tag = tg[t];
        p += em[t*CC + tag];
        if (t > 0) p += trans[tg[t-1]*CC + tag];
    }
#pragma unroll
    for (int off = 16; off; off >>= 1) p += __shfl_down_sync(0xffffffffu, p, off);
    float num = __shfl_sync(0xffffffffu, p, 0);
    num += startv[tg[0]] + endv[tg[TT-1]];

    int j = (lane < CC) ? lane : 0;
    float trc[CC];
#pragma unroll
    for (int i = 0; i < CC; i++) trc[i] = trans[i*CC + j];
    float alpha = startv[j] + em[j];
    float em_next = em[CC + j];
    for (int t = 1; t < TT; t++) {
        float a[CC];
#pragma unroll
        for (int i = 0; i < CC; i++) a[i] = __shfl_sync(0xffffffffu, alpha, i) + trc[i];
        float em_t = em_next;
        if (t < TT-1) em_next = em[(t+1)*CC + j];
        float mx = a[0];
#pragma unroll
        for (int i = 1; i < CC; i++) mx = fmaxf(mx, a[i]);
        float s = 0.f;
#pragma unroll
        for (int i = 0; i < CC; i++) s += expf(a[i] - mx);
        alpha = mx + logf(s) + em_t;
    }
    float v = alpha + endv[j];
    float mv = v;
#pragma unroll
    for (int i = 0; i < CC; i++) mv = fmaxf(mv, __shfl_sync(0xffffffffu, v, i));
    float se = expf(v - mv);
    float tot = 0.f;
#pragma unroll
    for (int i = 0; i < CC; i++) tot += __shfl_sync(0xffffffffu, se, i);
    float den = mv + logf(tot);
    if (lane == 0) g_llh[b] = num - den;
}

// ---------------- kernel 6: final reduction ----------------------------------
__global__ void k_final(float* out) {
    if (threadIdx.x == 0) {
        float s = 0.f;
        for (int i = 0; i < BB; i++) s += g_llh[i];
        out[0] = -s / (float)BB;
    }
}

// ---------------- launch ------------------------------------------------------
extern "C" void kernel_launch(void* const* d_in, const int* in_sizes, int n_in,
                              void* d_out, int out_size) {
    const int*   input  = (const int*)d_in[0];
    const int*   label  = (const int*)d_in[1];
    const float* emb    = (const float*)d_in[2];
    const float* w_ih_f = (const float*)d_in[3];
    const float* w_hh_f = (const float*)d_in[4];
    const float* b_ih_f = (const float*)d_in[5];
    const float* b_hh_f = (const float*)d_in[6];
    const float* w_ih_b = (const float*)d_in[7];
    const float* w_hh_b = (const float*)d_in[8];
    const float* b_ih_b = (const float*)d_in[9];
    const float* b_hh_b = (const float*)d_in[10];
    const float* cls_w  = (const float*)d_in[11];
    const float* cls_b  = (const float*)d_in[12];
    const float* startv = (const float*)d_in[13];
    const float* endv   = (const float*)d_in[14];
    const float* trans  = (const float*)d_in[15];

    cudaFuncSetAttribute(k_lstm, cudaFuncAttributeMaxDynamicSharedMemorySize, LSTM_SMEM_BYTES);
    cudaFuncSetAttribute(k_xpgemm_tc, cudaFuncAttributeMaxDynamicSharedMemorySize, XPG_SMEM_BYTES);

    k_gather<<<MTOT, 128>>>(input, emb);
    k_xpgemm_tc<<<dim3(32, 64), 256, XPG_SMEM_BYTES>>>(w_ih_f, w_ih_b, b_ih_f, b_hh_f, b_ih_b, b_hh_b);
    k_dummy<<<1, 32>>>();   // keeps ncu window on k_lstm
    k_lstm<<<LSTM_BLOCKS, 512, LSTM_SMEM_BYTES>>>(w_hh_f, w_hh_b);
    k_cls<<<MTOT, 288>>>(cls_w, cls_b);
    k_crf<<<BB, 32>>>(label, startv, endv, trans);
    k_final<<<1, 32>>>((float*)d_out);
}